// round 8
// baseline (speedup 1.0000x reference)
#include <cuda_runtime.h>
#include <math.h>
#include <cstdint>

#define NN 100000
#define EE 600000
#define DD 128
#define ETOT (EE + NN)
#define SCAN_B ((NN + 1023) / 1024)   // 98

// ---------------- scratch (static device globals; no allocation) ----------------
__device__ float    g_x0[NN * DD];
__device__ float    g_h [NN * DD];
__device__ float    g_el[NN * 4];
__device__ float    g_er[NN * 4];
__device__ float4   g_T [NN];
__device__ float    g_u [DD];
__device__ float    g_vb[DD];
__device__ float    g_sc[16];
__device__ unsigned g_elmax[8];      // ordered-uint float max: [layer(0/1)][head]
__device__ unsigned g_wmm[2];        // ordered-uint: [0]=max(w), [1]=min(w)
__device__ int      g_rowptr[NN + 1];
__device__ int      g_cnt[NN];
__device__ int      g_ps [NN];
__device__ int      g_bsum[SCAN_B];
__device__ int      g_boff[SCAN_B];
__device__ int      g_csr[ETOT];

// ordered-uint <-> float (monotone map so unsigned atomicMax/Min works)
__device__ __forceinline__ unsigned ford(float f) {
    unsigned u = __float_as_uint(f);
    return (u & 0x80000000u) ? ~u : (u | 0x80000000u);
}
__device__ __forceinline__ float funord(unsigned o) {
    return __uint_as_float((o & 0x80000000u) ? (o ^ 0x80000000u) : ~o);
}

// ---------------- CSR build ------------------------------------------------------
__global__ void k_hist(const int* __restrict__ dst) {
    int i = blockIdx.x * blockDim.x + threadIdx.x;
    if (i < EE) atomicAdd(&g_cnt[dst[i]], 1);
}

__global__ void __launch_bounds__(1024) k_scanA() {
    __shared__ int wsum[32];
    int tid = threadIdx.x, lane = tid & 31, warp = tid >> 5;
    int i = blockIdx.x * 1024 + tid;
    int c = (i < NN) ? g_cnt[i] + 1 : 0;   // +1 = self loop
    int v = c;
#pragma unroll
    for (int o = 1; o < 32; o <<= 1) {
        int t = __shfl_up_sync(0xffffffffu, v, o);
        if (lane >= o) v += t;
    }
    if (lane == 31) wsum[warp] = v;
    __syncthreads();
    if (warp == 0) {
        int w = wsum[lane];
#pragma unroll
        for (int o = 1; o < 32; o <<= 1) {
            int t = __shfl_up_sync(0xffffffffu, w, o);
            if (lane >= o) w += t;
        }
        wsum[lane] = w;
    }
    __syncthreads();
    int incl = v + (warp > 0 ? wsum[warp - 1] : 0);
    if (i < NN) g_ps[i] = incl;
    if (tid == 1023) g_bsum[blockIdx.x] = incl;
}

__global__ void k_scanB() {
    __shared__ int wsum[4];
    int tid = threadIdx.x, lane = tid & 31, warp = tid >> 5;
    int s = (tid < SCAN_B) ? g_bsum[tid] : 0;
    int v = s;
#pragma unroll
    for (int o = 1; o < 32; o <<= 1) {
        int t = __shfl_up_sync(0xffffffffu, v, o);
        if (lane >= o) v += t;
    }
    if (lane == 31) wsum[warp] = v;
    __syncthreads();
    int base = 0;
    for (int w = 0; w < warp; w++) base += wsum[w];
    int incl = v + base;
    if (tid < SCAN_B) g_boff[tid] = incl - s;
    if (tid == 127) g_rowptr[NN] = incl;
}

__global__ void __launch_bounds__(1024) k_scanC() {
    int i = blockIdx.x * 1024 + threadIdx.x;
    if (i < NN) {
        int c = g_cnt[i] + 1;
        int e = g_ps[i] - c + g_boff[blockIdx.x];
        g_rowptr[i] = e;
        g_cnt[i] = e;
    }
}

__global__ void k_scatter(const int* __restrict__ src, const int* __restrict__ dst) {
    int i = blockIdx.x * blockDim.x + threadIdx.x;
    if (i < EE) {
        int p = atomicAdd(&g_cnt[dst[i]], 1);
        g_csr[p] = src[i];
    } else if (i < EE + NN) {
        int n = i - EE;
        int p = atomicAdd(&g_cnt[n], 1);
        g_csr[p] = n;
    }
}

// ---------------- global weight min/max ------------------------------------------
__global__ void __launch_bounds__(256) k_wmm(const float* __restrict__ w) {
    int i = blockIdx.x * blockDim.x + threadIdx.x;
    float v = (i < NN) ? w[i] : w[0];
    float mx = v, mn = v;
#pragma unroll
    for (int o = 16; o > 0; o >>= 1) {
        mx = fmaxf(mx, __shfl_xor_sync(0xffffffffu, mx, o));
        mn = fminf(mn, __shfl_xor_sync(0xffffffffu, mn, o));
    }
    if ((threadIdx.x & 31) == 0) {
        atomicMax(&g_wmm[0], ford(mx));
        atomicMin(&g_wmm[1], ford(mn));
    }
}

// ---------------- layer-0 analytic prep ------------------------------------------
__global__ void __launch_bounds__(1024) k_prep(const float* __restrict__ fcW,
                                               const float* __restrict__ linW,
                                               const float* __restrict__ linb,
                                               const float* __restrict__ al,
                                               const float* __restrict__ ar,
                                               const float* __restrict__ cb) {
    __shared__ float su[128], sv[128];
    int tid = threadIdx.x;
    int d = tid >> 3, s = tid & 7;
    float uu = 0.f, vv = 0.f;
#pragma unroll
    for (int q = 0; q < 4; q++) {
        int k = s * 16 + q * 4;
        float4 w = *(const float4*)&fcW[d * 128 + k];
        float4 lw = *(const float4*)&linW[k];
        float4 lb = *(const float4*)&linb[k];
        uu = fmaf(w.x, lw.x, fmaf(w.y, lw.y, fmaf(w.z, lw.z, fmaf(w.w, lw.w, uu))));
        vv = fmaf(w.x, lb.x, fmaf(w.y, lb.y, fmaf(w.z, lb.z, fmaf(w.w, lb.w, vv))));
    }
#pragma unroll
    for (int o = 1; o <= 4; o <<= 1) {
        uu += __shfl_xor_sync(0xffffffffu, uu, o);
        vv += __shfl_xor_sync(0xffffffffu, vv, o);
    }
    if (s == 0) {
        su[d] = uu;
        sv[d] = vv;
        g_u[d] = uu;
        g_vb[d] = vv + cb[d];
    }
    __syncthreads();
    if (tid < 16) {
        int type = tid >> 2, h = tid & 3;
        const float* a = (type < 2) ? al : ar;
        const float* base = (type & 1) ? sv : su;
        float x = 0.f;
        for (int f = 0; f < 32; f++) x = fmaf(base[h * 32 + f], a[h * 32 + f], x);
        g_sc[type * 4 + h] = x;
    }
}

// ---------------- layer-0 aggregation (single pass, analytic max bound) ----------
__global__ void __launch_bounds__(256) k_agg0(const float* __restrict__ w) {
    int gw = (blockIdx.x * blockDim.x + threadIdx.x) >> 5;
    int lane = threadIdx.x & 31;
    if (gw >= NN) return;
    int n = gw;
    int beg = g_rowptr[n], end = g_rowptr[n + 1];

    float CL0 = g_sc[0], CL1 = g_sc[1], CL2 = g_sc[2], CL3 = g_sc[3];
    float DL0 = g_sc[4], DL1 = g_sc[5], DL2 = g_sc[6], DL3 = g_sc[7];
    float wn = w[n];
    float er0 = fmaf(wn, g_sc[8],  g_sc[12]);
    float er1 = fmaf(wn, g_sc[9],  g_sc[13]);
    float er2 = fmaf(wn, g_sc[10], g_sc[14]);
    float er3 = fmaf(wn, g_sc[11], g_sc[15]);

    float wmax = funord(g_wmm[0]), wmin = funord(g_wmm[1]);
    float m0 = fmaf(CL0 >= 0.f ? wmax : wmin, CL0, DL0) + er0; m0 = m0 >= 0.f ? m0 : 0.2f * m0;
    float m1 = fmaf(CL1 >= 0.f ? wmax : wmin, CL1, DL1) + er1; m1 = m1 >= 0.f ? m1 : 0.2f * m1;
    float m2 = fmaf(CL2 >= 0.f ? wmax : wmin, CL2, DL2) + er2; m2 = m2 >= 0.f ? m2 : 0.2f * m2;
    float m3 = fmaf(CL3 >= 0.f ? wmax : wmin, CL3, DL3) + er3; m3 = m3 >= 0.f ? m3 : 0.2f * m3;

    float S0 = 0.f, S1 = 0.f, S2 = 0.f, S3 = 0.f;
    float T0 = 0.f, T1 = 0.f, T2 = 0.f, T3 = 0.f;
    for (int j = beg + lane; j < end; j += 32) {
        float ws = w[g_csr[j]];
        float e0 = fmaf(ws, CL0, DL0) + er0; e0 = e0 >= 0.f ? e0 : 0.2f * e0;
        float e1 = fmaf(ws, CL1, DL1) + er1; e1 = e1 >= 0.f ? e1 : 0.2f * e1;
        float e2 = fmaf(ws, CL2, DL2) + er2; e2 = e2 >= 0.f ? e2 : 0.2f * e2;
        float e3 = fmaf(ws, CL3, DL3) + er3; e3 = e3 >= 0.f ? e3 : 0.2f * e3;
        float p0 = __expf(e0 - m0), p1 = __expf(e1 - m1);
        float p2 = __expf(e2 - m2), p3 = __expf(e3 - m3);
        S0 += p0; S1 += p1; S2 += p2; S3 += p3;
        T0 = fmaf(p0, ws, T0); T1 = fmaf(p1, ws, T1);
        T2 = fmaf(p2, ws, T2); T3 = fmaf(p3, ws, T3);
    }
#pragma unroll
    for (int o = 16; o > 0; o >>= 1) {
        S0 += __shfl_xor_sync(0xffffffffu, S0, o);
        S1 += __shfl_xor_sync(0xffffffffu, S1, o);
        S2 += __shfl_xor_sync(0xffffffffu, S2, o);
        S3 += __shfl_xor_sync(0xffffffffu, S3, o);
        T0 += __shfl_xor_sync(0xffffffffu, T0, o);
        T1 += __shfl_xor_sync(0xffffffffu, T1, o);
        T2 += __shfl_xor_sync(0xffffffffu, T2, o);
        T3 += __shfl_xor_sync(0xffffffffu, T3, o);
    }
    if (lane == 0)
        g_T[n] = make_float4(T0 / S0, T1 / S1, T2 / S2, T3 / S3);
}

// ---------------- GEMM h = leaky(x) @ W^T fused with el/er + el max -------------
template <int MODE>
__global__ void __launch_bounds__(256) k_gemm(const float* __restrict__ W,
                                              const float* __restrict__ al,
                                              const float* __restrict__ ar) {
    __shared__ float xs[64][33];
    __shared__ float ws[32][132];
    __shared__ float us[128], vbs[128];
    __shared__ float A4[64][4];
    __shared__ unsigned selmax[4];
    int tid = threadIdx.x;
    int tx = tid & 31, ty = tid >> 5;
    int row0 = blockIdx.x * 64;

    if (tid < 4) selmax[tid] = 0u;
    if (MODE == 0) {
        if (tid < 128) {
            us[tid] = g_u[tid];
            vbs[tid] = g_vb[tid];
        } else if (tid < 192) {
            int r = tid - 128;
            int grow = row0 + r;
            float4 a = (grow < NN) ? g_T[grow] : make_float4(0.f, 0.f, 0.f, 0.f);
            *(float4*)&A4[r][0] = a;
        }
    }
    __syncthreads();

    float acc[8][4];
#pragma unroll
    for (int r = 0; r < 8; r++)
#pragma unroll
        for (int c = 0; c < 4; c++) acc[r][c] = 0.f;

    for (int k0 = 0; k0 < 128; k0 += 32) {
        for (int i = tid; i < 64 * 32; i += 256) {
            int r = i >> 5, k = i & 31;
            int kk = k0 + k;
            float v;
            if (MODE == 0) {
                v = fmaf(A4[r][kk >> 5], us[kk], vbs[kk]);
            } else {
                int grow = row0 + r;
                v = (grow < NN) ? g_x0[grow * 128 + kk] : 0.f;
            }
            v = v >= 0.f ? v : 0.01f * v;
            xs[r][k] = v;
        }
        for (int i = tid; i < 128 * 32; i += 256) {
            int d = i >> 5, k = i & 31;
            ws[k][d] = W[d * 128 + k0 + k];
        }
        __syncthreads();
#pragma unroll
        for (int k = 0; k < 32; k++) {
            float4 b = *(const float4*)&ws[k][tx * 4];
#pragma unroll
            for (int r = 0; r < 8; r++) {
                float a = xs[ty * 8 + r][k];
                acc[r][0] = fmaf(a, b.x, acc[r][0]);
                acc[r][1] = fmaf(a, b.y, acc[r][1]);
                acc[r][2] = fmaf(a, b.z, acc[r][2]);
                acc[r][3] = fmaf(a, b.w, acc[r][3]);
            }
        }
        __syncthreads();
    }

    int col = tx * 4;
    float4 alv = *(const float4*)&al[col];
    float4 arv = *(const float4*)&ar[col];
    unsigned lmax = 0u;
#pragma unroll
    for (int r = 0; r < 8; r++) {
        int row = row0 + ty * 8 + r;
        float pl = acc[r][0] * alv.x + acc[r][1] * alv.y + acc[r][2] * alv.z + acc[r][3] * alv.w;
        float pr = acc[r][0] * arv.x + acc[r][1] * arv.y + acc[r][2] * arv.z + acc[r][3] * arv.w;
#pragma unroll
        for (int o = 4; o > 0; o >>= 1) {
            pl += __shfl_xor_sync(0xffffffffu, pl, o);
            pr += __shfl_xor_sync(0xffffffffu, pr, o);
        }
        if (row < NN) {
            *(float4*)&g_h[row * 128 + col] =
                make_float4(acc[r][0], acc[r][1], acc[r][2], acc[r][3]);
            if ((tx & 7) == 0) {
                int hh = tx >> 3;
                g_el[row * 4 + hh] = pl;
                g_er[row * 4 + hh] = pr;
                unsigned f = ford(pl);
                if (f > lmax) lmax = f;
            }
        }
    }
    if ((tx & 7) == 0 && lmax) atomicMax(&selmax[tx >> 3], lmax);
    __syncthreads();
    if (tid < 4 && selmax[tid]) atomicMax(&g_elmax[MODE * 4 + tid], selmax[tid]);
}

// ---------------- edge softmax + aggregation: shfl-broadcast edge pipeline ------
__device__ __forceinline__ float sel4(float4 v, int hh) {
    return (hh & 2) ? ((hh & 1) ? v.w : v.z) : ((hh & 1) ? v.y : v.x);
}

template <int FINAL>
__global__ void __launch_bounds__(256) k_agg(const float* __restrict__ bias,
                                             const float* __restrict__ pW,
                                             const float* __restrict__ pb,
                                             float* __restrict__ out) {
    int gw = (blockIdx.x * blockDim.x + threadIdx.x) >> 5;
    int lane = threadIdx.x & 31;
    if (gw >= NN) return;
    int n = gw;
    int beg = g_rowptr[n], end = g_rowptr[n + 1];
    int deg = end - beg;
    float4 er4 = *(const float4*)&g_er[n * 4];
    int hh = lane >> 3;

    // per-head upper-bound max (leaky is monotone)
    float4 m4;
    m4.x = funord(g_elmax[FINAL * 4 + 0]) + er4.x; m4.x = m4.x >= 0.f ? m4.x : 0.2f * m4.x;
    m4.y = funord(g_elmax[FINAL * 4 + 1]) + er4.y; m4.y = m4.y >= 0.f ? m4.y : 0.2f * m4.y;
    m4.z = funord(g_elmax[FINAL * 4 + 2]) + er4.z; m4.z = m4.z >= 0.f ? m4.z : 0.2f * m4.z;
    m4.w = funord(g_elmax[FINAL * 4 + 3]) + er4.w; m4.w = m4.w >= 0.f ? m4.w : 0.2f * m4.w;

    // lane-owned edge prefetch: index + all-head p values
    int eidx = beg + lane;
    int sl = 0;
    float4 p4 = make_float4(0.f, 0.f, 0.f, 0.f);
    if (eidx < end) {
        sl = g_csr[eidx];
        float4 el4 = *(const float4*)&g_el[sl * 4];
        float e0 = el4.x + er4.x; e0 = e0 >= 0.f ? e0 : 0.2f * e0;
        float e1 = el4.y + er4.y; e1 = e1 >= 0.f ? e1 : 0.2f * e1;
        float e2 = el4.z + er4.z; e2 = e2 >= 0.f ? e2 : 0.2f * e2;
        float e3 = el4.w + er4.w; e3 = e3 >= 0.f ? e3 : 0.2f * e3;
        p4 = make_float4(__expf(e0 - m4.x), __expf(e1 - m4.y),
                         __expf(e2 - m4.z), __expf(e3 - m4.w));
    }

    const float* __restrict__ hbase = g_h + (size_t)lane * 4;
    float a0 = 0.f, a1 = 0.f, a2 = 0.f, a3 = 0.f, sacc = 0.f;
    int cnt = deg < 32 ? deg : 32;
#pragma unroll 4
    for (int j = 0; j < cnt; j++) {
        int s = __shfl_sync(0xffffffffu, sl, j);
        float px = __shfl_sync(0xffffffffu, p4.x, j);
        float py = __shfl_sync(0xffffffffu, p4.y, j);
        float pz = __shfl_sync(0xffffffffu, p4.z, j);
        float pw_ = __shfl_sync(0xffffffffu, p4.w, j);
        float p = (hh & 2) ? ((hh & 1) ? pw_ : pz) : ((hh & 1) ? py : px);
        float4 hv = *(const float4*)&hbase[(size_t)s * 128];
        a0 = fmaf(p, hv.x, a0); a1 = fmaf(p, hv.y, a1);
        a2 = fmaf(p, hv.z, a2); a3 = fmaf(p, hv.w, a3);
        sacc += p;
    }
    if (deg > 32) {   // rare tail
        float mh = sel4(m4, hh), erh = sel4(er4, hh);
        for (int j = beg + 32; j < end; j++) {
            int s = g_csr[j];
            float4 el4 = *(const float4*)&g_el[s * 4];
            float e = sel4(el4, hh) + erh;
            e = e >= 0.f ? e : 0.2f * e;
            float p = __expf(e - mh);
            float4 hv = *(const float4*)&hbase[(size_t)s * 128];
            a0 = fmaf(p, hv.x, a0); a1 = fmaf(p, hv.y, a1);
            a2 = fmaf(p, hv.z, a2); a3 = fmaf(p, hv.w, a3);
            sacc += p;
        }
    }

    float inv = 1.f / sacc;
    int col = lane * 4;
    float4 bv = *(const float4*)&bias[col];
    float4 o = make_float4(fmaf(a0, inv, bv.x), fmaf(a1, inv, bv.y),
                           fmaf(a2, inv, bv.z), fmaf(a3, inv, bv.w));
    if (FINAL) {
        float4 wv = *(const float4*)&pW[col];
        float s = o.x * wv.x + o.y * wv.y + o.z * wv.z + o.w * wv.w;
#pragma unroll
        for (int of = 16; of > 0; of >>= 1) s += __shfl_xor_sync(0xffffffffu, s, of);
        if (lane == 0) out[n] = s + pb[0];
    } else {
        *(float4*)&g_x0[n * 128 + col] = o;
    }
}

// ---------------- launch --------------------------------------------------------
extern "C" void kernel_launch(void* const* d_in, const int* in_sizes, int n_in,
                              void* d_out, int out_size) {
    const float* weights = (const float*)d_in[0];
    const float* linW    = (const float*)d_in[1];
    const float* linb    = (const float*)d_in[2];
    const float* fcW     = (const float*)d_in[3];
    const float* al      = (const float*)d_in[4];
    const float* ar      = (const float*)d_in[5];
    const float* cb      = (const float*)d_in[6];
    const float* pW      = (const float*)d_in[7];
    const float* pb      = (const float*)d_in[8];
    const int*   src     = (const int*)d_in[9];
    const int*   dst     = (const int*)d_in[10];
    float* out = (float*)d_out;

    void* p = nullptr;
    cudaGetSymbolAddress(&p, g_cnt);
    cudaMemsetAsync(p, 0, NN * sizeof(int));
    cudaGetSymbolAddress(&p, g_elmax);
    cudaMemsetAsync(p, 0, 8 * sizeof(unsigned));
    cudaGetSymbolAddress(&p, g_wmm);
    cudaMemsetAsync(p, 0x00, sizeof(unsigned));
    cudaMemsetAsync((char*)p + sizeof(unsigned), 0xFF, sizeof(unsigned));

    k_hist<<<(EE + 255) / 256, 256>>>(dst);
    k_scanA<<<SCAN_B, 1024>>>();
    k_scanB<<<1, 128>>>();
    k_scanC<<<SCAN_B, 1024>>>();
    k_scatter<<<(EE + NN + 255) / 256, 256>>>(src, dst);

    k_wmm<<<(NN + 255) / 256, 256>>>(weights);
    k_prep<<<1, 1024>>>(fcW, linW, linb, al, ar, cb);

    const int GB = (NN + 63) / 64;
    const int AB = (NN * 32 + 255) / 256;

    k_agg0<<<AB, 256>>>(weights);
    k_gemm<0><<<GB, 256>>>(fcW + DD * DD, al + DD, ar + DD);
    k_agg<0><<<AB, 256>>>(cb + DD, pW, pb, out);
    k_gemm<1><<<GB, 256>>>(fcW + 2 * DD * DD, al + 2 * DD, ar + 2 * DD);
    k_agg<1><<<AB, 256>>>(cb + 2 * DD, pW, pb, out);
}

// round 10
// speedup vs baseline: 1.1683x; 1.1683x over previous
#include <cuda_runtime.h>
#include <math.h>
#include <cstdint>

#define NN 100000
#define EE 600000
#define DD 128
#define ETOT (EE + NN)
#define SCAN_B ((NN + 1023) / 1024)   // 98

// ---------------- scratch (static device globals; no allocation) ----------------
__device__ float    g_x0[NN * DD];    // y2 = leaky(out1)
__device__ float    g_h [NN * DD];    // h1
__device__ float    g_el[NN * 4];
__device__ float    g_er[NN * 4];
__device__ float4   g_T [NN];
__device__ float    g_u [DD];
__device__ float    g_vb[DD];
__device__ float    g_sc[16];
__device__ float    g_pl2[512];       // [h][k] projections of al2 through W2
__device__ float    g_pr2[512];
__device__ float    g_q  [512];       // [h][k] pW folded through W2
__device__ float    g_c0[1];
__device__ unsigned g_elmax[8];       // ordered-uint float max: [layer(0/1)][head]
__device__ unsigned g_wmm[2];
__device__ int      g_rowptr[NN + 1];
__device__ int      g_cnt[NN];
__device__ int      g_ps [NN];
__device__ int      g_bsum[SCAN_B];
__device__ int      g_boff[SCAN_B];
__device__ int      g_csr[ETOT];

__device__ __forceinline__ unsigned ford(float f) {
    unsigned u = __float_as_uint(f);
    return (u & 0x80000000u) ? ~u : (u | 0x80000000u);
}
__device__ __forceinline__ float funord(unsigned o) {
    return __uint_as_float((o & 0x80000000u) ? (o ^ 0x80000000u) : ~o);
}

// ---------------- CSR build ------------------------------------------------------
__global__ void k_hist(const int* __restrict__ dst) {
    int i = blockIdx.x * blockDim.x + threadIdx.x;
    if (i < EE) atomicAdd(&g_cnt[dst[i]], 1);
}

__global__ void __launch_bounds__(1024) k_scanA() {
    __shared__ int wsum[32];
    int tid = threadIdx.x, lane = tid & 31, warp = tid >> 5;
    int i = blockIdx.x * 1024 + tid;
    int c = (i < NN) ? g_cnt[i] + 1 : 0;
    int v = c;
#pragma unroll
    for (int o = 1; o < 32; o <<= 1) {
        int t = __shfl_up_sync(0xffffffffu, v, o);
        if (lane >= o) v += t;
    }
    if (lane == 31) wsum[warp] = v;
    __syncthreads();
    if (warp == 0) {
        int w = wsum[lane];
#pragma unroll
        for (int o = 1; o < 32; o <<= 1) {
            int t = __shfl_up_sync(0xffffffffu, w, o);
            if (lane >= o) w += t;
        }
        wsum[lane] = w;
    }
    __syncthreads();
    int incl = v + (warp > 0 ? wsum[warp - 1] : 0);
    if (i < NN) g_ps[i] = incl;
    if (tid == 1023) g_bsum[blockIdx.x] = incl;
}

__global__ void k_scanB() {
    __shared__ int wsum[4];
    int tid = threadIdx.x, lane = tid & 31, warp = tid >> 5;
    int s = (tid < SCAN_B) ? g_bsum[tid] : 0;
    int v = s;
#pragma unroll
    for (int o = 1; o < 32; o <<= 1) {
        int t = __shfl_up_sync(0xffffffffu, v, o);
        if (lane >= o) v += t;
    }
    if (lane == 31) wsum[warp] = v;
    __syncthreads();
    int base = 0;
    for (int w = 0; w < warp; w++) base += wsum[w];
    int incl = v + base;
    if (tid < SCAN_B) g_boff[tid] = incl - s;
    if (tid == 127) g_rowptr[NN] = incl;
}

__global__ void __launch_bounds__(1024) k_scanC() {
    int i = blockIdx.x * 1024 + threadIdx.x;
    if (i < NN) {
        int c = g_cnt[i] + 1;
        int e = g_ps[i] - c + g_boff[blockIdx.x];
        g_rowptr[i] = e;
        g_cnt[i] = e;
    }
}

__global__ void k_scatter(const int* __restrict__ src, const int* __restrict__ dst) {
    int i = blockIdx.x * blockDim.x + threadIdx.x;
    if (i < EE) {
        int p = atomicAdd(&g_cnt[dst[i]], 1);
        g_csr[p] = src[i];
    } else if (i < EE + NN) {
        int n = i - EE;
        int p = atomicAdd(&g_cnt[n], 1);
        g_csr[p] = n;
    }
}

// ---------------- global weight min/max ------------------------------------------
__global__ void __launch_bounds__(256) k_wmm(const float* __restrict__ w) {
    int i = blockIdx.x * blockDim.x + threadIdx.x;
    float v = (i < NN) ? w[i] : w[0];
    float mx = v, mn = v;
#pragma unroll
    for (int o = 16; o > 0; o >>= 1) {
        mx = fmaxf(mx, __shfl_xor_sync(0xffffffffu, mx, o));
        mn = fminf(mn, __shfl_xor_sync(0xffffffffu, mn, o));
    }
    if ((threadIdx.x & 31) == 0) {
        atomicMax(&g_wmm[0], ford(mx));
        atomicMin(&g_wmm[1], ford(mn));
    }
}

// ---------------- layer-0 analytic prep ------------------------------------------
__global__ void __launch_bounds__(1024) k_prep(const float* __restrict__ fcW,
                                               const float* __restrict__ linW,
                                               const float* __restrict__ linb,
                                               const float* __restrict__ al,
                                               const float* __restrict__ ar,
                                               const float* __restrict__ cb) {
    __shared__ float su[128], sv[128];
    int tid = threadIdx.x;
    int d = tid >> 3, s = tid & 7;
    float uu = 0.f, vv = 0.f;
#pragma unroll
    for (int q = 0; q < 4; q++) {
        int k = s * 16 + q * 4;
        float4 w = *(const float4*)&fcW[d * 128 + k];
        float4 lw = *(const float4*)&linW[k];
        float4 lb = *(const float4*)&linb[k];
        uu = fmaf(w.x, lw.x, fmaf(w.y, lw.y, fmaf(w.z, lw.z, fmaf(w.w, lw.w, uu))));
        vv = fmaf(w.x, lb.x, fmaf(w.y, lb.y, fmaf(w.z, lb.z, fmaf(w.w, lb.w, vv))));
    }
#pragma unroll
    for (int o = 1; o <= 4; o <<= 1) {
        uu += __shfl_xor_sync(0xffffffffu, uu, o);
        vv += __shfl_xor_sync(0xffffffffu, vv, o);
    }
    if (s == 0) {
        su[d] = uu;
        sv[d] = vv;
        g_u[d] = uu;
        g_vb[d] = vv + cb[d];
    }
    __syncthreads();
    if (tid < 16) {
        int type = tid >> 2, h = tid & 3;
        const float* a = (type < 2) ? al : ar;
        const float* base = (type & 1) ? sv : su;
        float x = 0.f;
        for (int f = 0; f < 32; f++) x = fmaf(base[h * 32 + f], a[h * 32 + f], x);
        g_sc[type * 4 + h] = x;
    }
}

// ---------------- layer-2 projection prep ----------------------------------------
// pl2[h][k] = sum_f al2[h,f] W2[h*32+f, k]; pr2 likewise; q[h][k] = sum_f pW[h*32+f] W2[h*32+f,k]
__global__ void __launch_bounds__(512) k_proj(const float* __restrict__ W2,
                                              const float* __restrict__ al2,
                                              const float* __restrict__ ar2,
                                              const float* __restrict__ pW,
                                              const float* __restrict__ pb,
                                              const float* __restrict__ b2) {
    int tid = threadIdx.x;
    int h = tid >> 7, k = tid & 127;
    float sl = 0.f, sr = 0.f, sq = 0.f;
#pragma unroll 4
    for (int f = 0; f < 32; f++) {
        float w = W2[(h * 32 + f) * 128 + k];
        sl = fmaf(al2[h * 32 + f], w, sl);
        sr = fmaf(ar2[h * 32 + f], w, sr);
        sq = fmaf(pW[h * 32 + f], w, sq);
    }
    g_pl2[tid] = sl;
    g_pr2[tid] = sr;
    g_q[tid] = sq;
    if (tid == 0) {
        float c = pb[0];
        for (int cc = 0; cc < 128; cc++) c = fmaf(pW[cc], b2[cc], c);
        g_c0[0] = c;
    }
}

// ---------------- layer-0 aggregation (single pass, analytic max bound) ----------
__global__ void __launch_bounds__(256) k_agg0(const float* __restrict__ w) {
    int gw = (blockIdx.x * blockDim.x + threadIdx.x) >> 5;
    int lane = threadIdx.x & 31;
    if (gw >= NN) return;
    int n = gw;
    int beg = g_rowptr[n], end = g_rowptr[n + 1];

    float CL0 = g_sc[0], CL1 = g_sc[1], CL2 = g_sc[2], CL3 = g_sc[3];
    float DL0 = g_sc[4], DL1 = g_sc[5], DL2 = g_sc[6], DL3 = g_sc[7];
    float wn = w[n];
    float er0 = fmaf(wn, g_sc[8],  g_sc[12]);
    float er1 = fmaf(wn, g_sc[9],  g_sc[13]);
    float er2 = fmaf(wn, g_sc[10], g_sc[14]);
    float er3 = fmaf(wn, g_sc[11], g_sc[15]);

    float wmax = funord(g_wmm[0]), wmin = funord(g_wmm[1]);
    float m0 = fmaf(CL0 >= 0.f ? wmax : wmin, CL0, DL0) + er0; m0 = m0 >= 0.f ? m0 : 0.2f * m0;
    float m1 = fmaf(CL1 >= 0.f ? wmax : wmin, CL1, DL1) + er1; m1 = m1 >= 0.f ? m1 : 0.2f * m1;
    float m2 = fmaf(CL2 >= 0.f ? wmax : wmin, CL2, DL2) + er2; m2 = m2 >= 0.f ? m2 : 0.2f * m2;
    float m3 = fmaf(CL3 >= 0.f ? wmax : wmin, CL3, DL3) + er3; m3 = m3 >= 0.f ? m3 : 0.2f * m3;

    float S0 = 0.f, S1 = 0.f, S2 = 0.f, S3 = 0.f;
    float T0 = 0.f, T1 = 0.f, T2 = 0.f, T3 = 0.f;
    for (int j = beg + lane; j < end; j += 32) {
        float ws = w[g_csr[j]];
        float e0 = fmaf(ws, CL0, DL0) + er0; e0 = e0 >= 0.f ? e0 : 0.2f * e0;
        float e1 = fmaf(ws, CL1, DL1) + er1; e1 = e1 >= 0.f ? e1 : 0.2f * e1;
        float e2 = fmaf(ws, CL2, DL2) + er2; e2 = e2 >= 0.f ? e2 : 0.2f * e2;
        float e3 = fmaf(ws, CL3, DL3) + er3; e3 = e3 >= 0.f ? e3 : 0.2f * e3;
        float p0 = __expf(e0 - m0), p1 = __expf(e1 - m1);
        float p2 = __expf(e2 - m2), p3 = __expf(e3 - m3);
        S0 += p0; S1 += p1; S2 += p2; S3 += p3;
        T0 = fmaf(p0, ws, T0); T1 = fmaf(p1, ws, T1);
        T2 = fmaf(p2, ws, T2); T3 = fmaf(p3, ws, T3);
    }
#pragma unroll
    for (int o = 16; o > 0; o >>= 1) {
        S0 += __shfl_xor_sync(0xffffffffu, S0, o);
        S1 += __shfl_xor_sync(0xffffffffu, S1, o);
        S2 += __shfl_xor_sync(0xffffffffu, S2, o);
        S3 += __shfl_xor_sync(0xffffffffu, S3, o);
        T0 += __shfl_xor_sync(0xffffffffu, T0, o);
        T1 += __shfl_xor_sync(0xffffffffu, T1, o);
        T2 += __shfl_xor_sync(0xffffffffu, T2, o);
        T3 += __shfl_xor_sync(0xffffffffu, T3, o);
    }
    if (lane == 0)
        g_T[n] = make_float4(T0 / S0, T1 / S1, T2 / S2, T3 / S3);
}

// ---------------- layer-1 GEMM h1 = W1 @ y1, y1 from g_T; fused el/er + elmax ---
__global__ void __launch_bounds__(256) k_gemm(const float* __restrict__ W,
                                              const float* __restrict__ al,
                                              const float* __restrict__ ar) {
    __shared__ float xs[64][33];
    __shared__ float ws[32][132];
    __shared__ float us[128], vbs[128];
    __shared__ float A4[64][4];
    __shared__ unsigned selmax[4];
    int tid = threadIdx.x;
    int tx = tid & 31, ty = tid >> 5;
    int row0 = blockIdx.x * 64;

    if (tid < 4) selmax[tid] = 0u;
    if (tid < 128) {
        us[tid] = g_u[tid];
        vbs[tid] = g_vb[tid];
    } else if (tid < 192) {
        int r = tid - 128;
        int grow = row0 + r;
        float4 a = (grow < NN) ? g_T[grow] : make_float4(0.f, 0.f, 0.f, 0.f);
        *(float4*)&A4[r][0] = a;
    }
    __syncthreads();

    float acc[8][4];
#pragma unroll
    for (int r = 0; r < 8; r++)
#pragma unroll
        for (int c = 0; c < 4; c++) acc[r][c] = 0.f;

    for (int k0 = 0; k0 < 128; k0 += 32) {
        for (int i = tid; i < 64 * 32; i += 256) {
            int r = i >> 5, k = i & 31;
            int kk = k0 + k;
            float v = fmaf(A4[r][kk >> 5], us[kk], vbs[kk]);
            v = v >= 0.f ? v : 0.01f * v;
            xs[r][k] = v;
        }
        for (int i = tid; i < 128 * 32; i += 256) {
            int d = i >> 5, k = i & 31;
            ws[k][d] = W[d * 128 + k0 + k];
        }
        __syncthreads();
#pragma unroll
        for (int k = 0; k < 32; k++) {
            float4 b = *(const float4*)&ws[k][tx * 4];
#pragma unroll
            for (int r = 0; r < 8; r++) {
                float a = xs[ty * 8 + r][k];
                acc[r][0] = fmaf(a, b.x, acc[r][0]);
                acc[r][1] = fmaf(a, b.y, acc[r][1]);
                acc[r][2] = fmaf(a, b.z, acc[r][2]);
                acc[r][3] = fmaf(a, b.w, acc[r][3]);
            }
        }
        __syncthreads();
    }

    int col = tx * 4;
    float4 alv = *(const float4*)&al[col];
    float4 arv = *(const float4*)&ar[col];
    unsigned lmax = 0u;
#pragma unroll
    for (int r = 0; r < 8; r++) {
        int row = row0 + ty * 8 + r;
        float pl = acc[r][0] * alv.x + acc[r][1] * alv.y + acc[r][2] * alv.z + acc[r][3] * alv.w;
        float pr = acc[r][0] * arv.x + acc[r][1] * arv.y + acc[r][2] * arv.z + acc[r][3] * arv.w;
#pragma unroll
        for (int o = 4; o > 0; o >>= 1) {
            pl += __shfl_xor_sync(0xffffffffu, pl, o);
            pr += __shfl_xor_sync(0xffffffffu, pr, o);
        }
        if (row < NN) {
            *(float4*)&g_h[row * 128 + col] =
                make_float4(acc[r][0], acc[r][1], acc[r][2], acc[r][3]);
            if ((tx & 7) == 0) {
                int hh = tx >> 3;
                g_el[row * 4 + hh] = pl;
                g_er[row * 4 + hh] = pr;
                unsigned f = ford(pl);
                if (f > lmax) lmax = f;
            }
        }
    }
    if ((tx & 7) == 0 && lmax) atomicMax(&selmax[tx >> 3], lmax);
    __syncthreads();
    if (tid < 4 && selmax[tid]) atomicMax(&g_elmax[tid], selmax[tid]);
}

// ---------------- layer-1 aggregation: y2 = leaky(sum alpha h1 + b1, 0.01) ------
__device__ __forceinline__ float sel4(float4 v, int hh) {
    return (hh & 2) ? ((hh & 1) ? v.w : v.z) : ((hh & 1) ? v.y : v.x);
}

__global__ void __launch_bounds__(256) k_agg1(const float* __restrict__ bias) {
    int gw = (blockIdx.x * blockDim.x + threadIdx.x) >> 5;
    int lane = threadIdx.x & 31;
    if (gw >= NN) return;
    int n = gw;
    int beg = g_rowptr[n], end = g_rowptr[n + 1];
    float4 er4 = *(const float4*)&g_er[n * 4];

    int hh = lane >> 3;
    float erh = sel4(er4, hh);
    float mh = funord(g_elmax[hh]) + erh;
    mh = mh >= 0.f ? mh : 0.2f * mh;

    float a0 = 0.f, a1 = 0.f, a2 = 0.f, a3 = 0.f, sacc = 0.f;
    for (int j = beg; j < end; j++) {
        int s = g_csr[j];
        float4 el4 = *(const float4*)&g_el[s * 4];
        float e = sel4(el4, hh) + erh;
        e = e >= 0.f ? e : 0.2f * e;
        float p = __expf(e - mh);
        float4 hv = *(const float4*)&g_h[s * 128 + lane * 4];
        a0 = fmaf(p, hv.x, a0); a1 = fmaf(p, hv.y, a1);
        a2 = fmaf(p, hv.z, a2); a3 = fmaf(p, hv.w, a3);
        sacc += p;
    }
    float inv = 1.f / sacc;
    int col = lane * 4;
    float4 bv = *(const float4*)&bias[col];
    float ox = fmaf(a0, inv, bv.x), oy = fmaf(a1, inv, bv.y);
    float oz = fmaf(a2, inv, bv.z), ow = fmaf(a3, inv, bv.w);
    ox = ox >= 0.f ? ox : 0.01f * ox;   // leaky before next layer
    oy = oy >= 0.f ? oy : 0.01f * oy;
    oz = oz >= 0.f ? oz : 0.01f * oz;
    ow = ow >= 0.f ? ow : 0.01f * ow;
    *(float4*)&g_x0[n * 128 + col] = make_float4(ox, oy, oz, ow);
}

// ---------------- layer-2 attention: el2/er2 = y2 . pl2_h / pr2_h + elmax -------
__global__ void __launch_bounds__(256) k_att2() {
    __shared__ float spl[512], spr[512];
    __shared__ unsigned selmax[4];
    int tid = threadIdx.x;
    if (tid < 4) selmax[tid] = 0u;
    spl[tid] = g_pl2[tid];       spl[tid + 256] = g_pl2[tid + 256];
    spr[tid] = g_pr2[tid];       spr[tid + 256] = g_pr2[tid + 256];
    __syncthreads();

    int gw = (blockIdx.x * 256 + tid) >> 5;
    int lane = tid & 31;
    if (gw < NN) {
        int c = lane * 4;
        float4 y = *(const float4*)&g_x0[gw * 128 + c];
        float el[4], er[4];
#pragma unroll
        for (int h = 0; h < 4; h++) {
            const float* pl = spl + h * 128 + c;
            const float* pr = spr + h * 128 + c;
            el[h] = y.x * pl[0] + y.y * pl[1] + y.z * pl[2] + y.w * pl[3];
            er[h] = y.x * pr[0] + y.y * pr[1] + y.z * pr[2] + y.w * pr[3];
        }
#pragma unroll
        for (int o = 16; o > 0; o >>= 1) {
#pragma unroll
            for (int h = 0; h < 4; h++) {
                el[h] += __shfl_xor_sync(0xffffffffu, el[h], o);
                er[h] += __shfl_xor_sync(0xffffffffu, er[h], o);
            }
        }
        if (lane == 0) {
            *(float4*)&g_el[gw * 4] = make_float4(el[0], el[1], el[2], el[3]);
            *(float4*)&g_er[gw * 4] = make_float4(er[0], er[1], er[2], er[3]);
#pragma unroll
            for (int h = 0; h < 4; h++) atomicMax(&selmax[h], ford(el[h]));
        }
    }
    __syncthreads();
    if (tid < 4 && selmax[tid]) atomicMax(&g_elmax[4 + tid], selmax[tid]);
}

// ---------------- final: logits = sum_h (sum_s alpha_sh (q_h . y2[s])) / S_h + c0
__global__ void __launch_bounds__(256) k_aggF(float* __restrict__ out) {
    __shared__ float sq[512];
    int tid = threadIdx.x;
    sq[tid] = g_q[tid];
    sq[tid + 256] = g_q[tid + 256];
    __syncthreads();

    int gw = (blockIdx.x * 256 + tid) >> 5;
    int lane = tid & 31;
    if (gw >= NN) return;
    int n = gw;
    int beg = g_rowptr[n], end = g_rowptr[n + 1];
    float4 er4 = *(const float4*)&g_er[n * 4];

    int c = lane * 4;
    float q0x = sq[c],       q0y = sq[c + 1],       q0z = sq[c + 2],       q0w = sq[c + 3];
    float q1x = sq[128 + c], q1y = sq[129 + c],     q1z = sq[130 + c],     q1w = sq[131 + c];
    float q2x = sq[256 + c], q2y = sq[257 + c],     q2z = sq[258 + c],     q2w = sq[259 + c];
    float q3x = sq[384 + c], q3y = sq[385 + c],     q3z = sq[386 + c],     q3w = sq[387 + c];

    float m0 = funord(g_elmax[4]) + er4.x; m0 = m0 >= 0.f ? m0 : 0.2f * m0;
    float m1 = funord(g_elmax[5]) + er4.y; m1 = m1 >= 0.f ? m1 : 0.2f * m1;
    float m2 = funord(g_elmax[6]) + er4.z; m2 = m2 >= 0.f ? m2 : 0.2f * m2;
    float m3 = funord(g_elmax[7]) + er4.w; m3 = m3 >= 0.f ? m3 : 0.2f * m3;

    float t0 = 0.f, t1 = 0.f, t2 = 0.f, t3 = 0.f;
    float S0 = 0.f, S1 = 0.f, S2 = 0.f, S3 = 0.f;
    for (int j = beg; j < end; j++) {
        int s = g_csr[j];
        float4 el4 = *(const float4*)&g_el[s * 4];
        float e0 = el4.x + er4.x; e0 = e0 >= 0.f ? e0 : 0.2f * e0;
        float e1 = el4.y + er4.y; e1 = e1 >= 0.f ? e1 : 0.2f * e1;
        float e2 = el4.z + er4.z; e2 = e2 >= 0.f ? e2 : 0.2f * e2;
        float e3 = el4.w + er4.w; e3 = e3 >= 0.f ? e3 : 0.2f * e3;
        float p0 = __expf(e0 - m0), p1 = __expf(e1 - m1);
        float p2 = __expf(e2 - m2), p3 = __expf(e3 - m3);
        float4 y = *(const float4*)&g_x0[(size_t)s * 128 + c];
        t0 = fmaf(p0, y.x * q0x + y.y * q0y + y.z * q0z + y.w * q0w, t0);
        t1 = fmaf(p1, y.x * q1x + y.y * q1y + y.z * q1z + y.w * q1w, t1);
        t2 = fmaf(p2, y.x * q2x + y.y * q2y + y.z * q2z + y.w * q2w, t2);
        t3 = fmaf(p3, y.x * q3x + y.y * q3y + y.z * q3z + y.w * q3w, t3);
        S0 += p0; S1 += p1; S2 += p2; S3 += p3;
    }
    float t = t0 / S0 + t1 / S1 + t2 / S2 + t3 / S3;
#pragma unroll
    for (int o = 16; o > 0; o >>= 1) t += __shfl_xor_sync(0xffffffffu, t, o);
    if (lane == 0) out[n] = t + g_c0[0];
}

// ---------------- launch --------------------------------------------------------
extern "C" void kernel_launch(void* const* d_in, const int* in_sizes, int n_in,
                              void* d_out, int out_size) {
    const float* weights = (const float*)d_in[0];
    const float* linW    = (const float*)d_in[1];
    const float* linb    = (const float*)d_in[2];
    const float* fcW     = (const float*)d_in[3];
    const float* al      = (const float*)d_in[4];
    const float* ar      = (const float*)d_in[5];
    const float* cb      = (const float*)d_in[6];
    const float* pW      = (const float*)d_in[7];
    const float* pb      = (const float*)d_in[8];
    const int*   src     = (const int*)d_in[9];
    const int*   dst     = (const int*)d_in[10];
    float* out = (float*)d_out;

    void* p = nullptr;
    cudaGetSymbolAddress(&p, g_cnt);
    cudaMemsetAsync(p, 0, NN * sizeof(int));
    cudaGetSymbolAddress(&p, g_elmax);
    cudaMemsetAsync(p, 0, 8 * sizeof(unsigned));
    cudaGetSymbolAddress(&p, g_wmm);
    cudaMemsetAsync(p, 0x00, sizeof(unsigned));
    cudaMemsetAsync((char*)p + sizeof(unsigned), 0xFF, sizeof(unsigned));

    k_hist<<<(EE + 255) / 256, 256>>>(dst);
    k_scanA<<<SCAN_B, 1024>>>();
    k_scanB<<<1, 128>>>();
    k_scanC<<<SCAN_B, 1024>>>();
    k_scatter<<<(EE + NN + 255) / 256, 256>>>(src, dst);

    k_wmm<<<(NN + 255) / 256, 256>>>(weights);
    k_prep<<<1, 1024>>>(fcW, linW, linb, al, ar, cb);
    k_proj<<<1, 512>>>(fcW + 2 * DD * DD, al + 2 * DD, ar + 2 * DD, pW, pb, cb + 2 * DD);

    const int GB = (NN + 63) / 64;
    const int AB = (NN * 32 + 255) / 256;

    k_agg0<<<AB, 256>>>(weights);
    k_gemm<<<GB, 256>>>(fcW + DD * DD, al + DD, ar + DD);
    k_agg1<<<AB, 256>>>(cb + DD);
    k_att2<<<AB, 256>>>();
    k_aggF<<<AB, 256>>>(out);
}

// round 13
// speedup vs baseline: 1.3339x; 1.1418x over previous
#include <cuda_runtime.h>
#include <math.h>
#include <cstdint>

#define NN 100000
#define EE 600000
#define DD 128
#define ETOT (EE + NN)
#define SCAN_B ((NN + 1023) / 1024)   // 98

// ---------------- scratch (static device globals; no allocation) ----------------
__device__ float    g_x0[NN * DD];    // y2 = leaky(out1)
__device__ float    g_h [NN * DD];    // h1
__device__ float    g_el[NN * 4];
__device__ float    g_er[NN * 4];
__device__ float4   g_T [NN];
__device__ float    g_u [DD];
__device__ float    g_vb[DD];
__device__ float    g_sc[16];
__device__ float    g_pl2[512];
__device__ float    g_pr2[512];
__device__ float    g_q  [512];
__device__ float    g_c0[1];
// piecewise-linear layer-1 tables
__device__ float    g_D1[4 * 33 * 128];
__device__ float    g_D2[4 * 33 * 128];
__device__ float    g_P [4 * 128];
__device__ float    g_Q [128];
__device__ float    g_Cc[128];
__device__ float    g_ts[128];        // [h][32] sorted breakpoints
__device__ unsigned g_elmax[8];
__device__ unsigned g_wmm[2];
__device__ int      g_rowptr[NN + 1];
__device__ int      g_cnt[NN];
__device__ int      g_ps [NN];
__device__ int      g_bsum[SCAN_B];
__device__ int      g_boff[SCAN_B];
__device__ int      g_csr[ETOT];

__device__ __forceinline__ unsigned ford(float f) {
    unsigned u = __float_as_uint(f);
    return (u & 0x80000000u) ? ~u : (u | 0x80000000u);
}
__device__ __forceinline__ float funord(unsigned o) {
    return __uint_as_float((o & 0x80000000u) ? (o ^ 0x80000000u) : ~o);
}

// ---------------- CSR build ------------------------------------------------------
__global__ void k_hist(const int* __restrict__ dst) {
    int i = blockIdx.x * blockDim.x + threadIdx.x;
    if (i < EE) atomicAdd(&g_cnt[dst[i]], 1);
}

__global__ void __launch_bounds__(1024) k_scanA() {
    __shared__ int wsum[32];
    int tid = threadIdx.x, lane = tid & 31, warp = tid >> 5;
    int i = blockIdx.x * 1024 + tid;
    int c = (i < NN) ? g_cnt[i] + 1 : 0;
    int v = c;
#pragma unroll
    for (int o = 1; o < 32; o <<= 1) {
        int t = __shfl_up_sync(0xffffffffu, v, o);
        if (lane >= o) v += t;
    }
    if (lane == 31) wsum[warp] = v;
    __syncthreads();
    if (warp == 0) {
        int w = wsum[lane];
#pragma unroll
        for (int o = 1; o < 32; o <<= 1) {
            int t = __shfl_up_sync(0xffffffffu, w, o);
            if (lane >= o) w += t;
        }
        wsum[lane] = w;
    }
    __syncthreads();
    int incl = v + (warp > 0 ? wsum[warp - 1] : 0);
    if (i < NN) g_ps[i] = incl;
    if (tid == 1023) g_bsum[blockIdx.x] = incl;
}

__global__ void k_scanB() {
    __shared__ int wsum[4];
    int tid = threadIdx.x, lane = tid & 31, warp = tid >> 5;
    int s = (tid < SCAN_B) ? g_bsum[tid] : 0;
    int v = s;
#pragma unroll
    for (int o = 1; o < 32; o <<= 1) {
        int t = __shfl_up_sync(0xffffffffu, v, o);
        if (lane >= o) v += t;
    }
    if (lane == 31) wsum[warp] = v;
    __syncthreads();
    int base = 0;
    for (int w = 0; w < warp; w++) base += wsum[w];
    int incl = v + base;
    if (tid < SCAN_B) g_boff[tid] = incl - s;
    if (tid == 127) g_rowptr[NN] = incl;
}

__global__ void __launch_bounds__(1024) k_scanC() {
    int i = blockIdx.x * 1024 + threadIdx.x;
    if (i < NN) {
        int c = g_cnt[i] + 1;
        int e = g_ps[i] - c + g_boff[blockIdx.x];
        g_rowptr[i] = e;
        g_cnt[i] = e;
    }
}

__global__ void k_scatter(const int* __restrict__ src, const int* __restrict__ dst) {
    int i = blockIdx.x * blockDim.x + threadIdx.x;
    if (i < EE) {
        int p = atomicAdd(&g_cnt[dst[i]], 1);
        g_csr[p] = src[i];
    } else if (i < EE + NN) {
        int n = i - EE;
        int p = atomicAdd(&g_cnt[n], 1);
        g_csr[p] = n;
    }
}

// ---------------- global weight min/max ------------------------------------------
__global__ void __launch_bounds__(256) k_wmm(const float* __restrict__ w) {
    int i = blockIdx.x * blockDim.x + threadIdx.x;
    float v = (i < NN) ? w[i] : w[0];
    float mx = v, mn = v;
#pragma unroll
    for (int o = 16; o > 0; o >>= 1) {
        mx = fmaxf(mx, __shfl_xor_sync(0xffffffffu, mx, o));
        mn = fminf(mn, __shfl_xor_sync(0xffffffffu, mn, o));
    }
    if ((threadIdx.x & 31) == 0) {
        atomicMax(&g_wmm[0], ford(mx));
        atomicMin(&g_wmm[1], ford(mn));
    }
}

// ---------------- layer-0 analytic prep ------------------------------------------
__global__ void __launch_bounds__(1024) k_prep(const float* __restrict__ fcW,
                                               const float* __restrict__ linW,
                                               const float* __restrict__ linb,
                                               const float* __restrict__ al,
                                               const float* __restrict__ ar,
                                               const float* __restrict__ cb) {
    __shared__ float su[128], sv[128];
    int tid = threadIdx.x;
    int d = tid >> 3, s = tid & 7;
    float uu = 0.f, vv = 0.f;
#pragma unroll
    for (int q = 0; q < 4; q++) {
        int k = s * 16 + q * 4;
        float4 w = *(const float4*)&fcW[d * 128 + k];
        float4 lw = *(const float4*)&linW[k];
        float4 lb = *(const float4*)&linb[k];
        uu = fmaf(w.x, lw.x, fmaf(w.y, lw.y, fmaf(w.z, lw.z, fmaf(w.w, lw.w, uu))));
        vv = fmaf(w.x, lb.x, fmaf(w.y, lb.y, fmaf(w.z, lb.z, fmaf(w.w, lb.w, vv))));
    }
#pragma unroll
    for (int o = 1; o <= 4; o <<= 1) {
        uu += __shfl_xor_sync(0xffffffffu, uu, o);
        vv += __shfl_xor_sync(0xffffffffu, vv, o);
    }
    if (s == 0) {
        su[d] = uu;
        sv[d] = vv;
        g_u[d] = uu;
        g_vb[d] = vv + cb[d];
    }
    __syncthreads();
    if (tid < 16) {
        int type = tid >> 2, h = tid & 3;
        const float* a = (type < 2) ? al : ar;
        const float* base = (type & 1) ? sv : su;
        float x = 0.f;
        for (int f = 0; f < 32; f++) x = fmaf(base[h * 32 + f], a[h * 32 + f], x);
        g_sc[type * 4 + h] = x;
    }
}

// ---------------- layer-1 piecewise tables (needs g_u, g_vb) ---------------------
__global__ void __launch_bounds__(128) k_prep2(const float* __restrict__ W1) {
    __shared__ float t_s[128], au_s[128], avb_s[128], u_s[128], vb_s[128];
    __shared__ int perm[4][32];
    int d = threadIdx.x;
    float u = g_u[d], vb = g_vb[d];
    float au = fabsf(u);
    int z = (au < 1e-30f);
    u_s[d] = u;
    vb_s[d] = vb;
    t_s[d] = z ? 0.f : (-vb / u);
    au_s[d] = z ? 0.f : au;
    avb_s[d] = z ? fabsf(vb) : 0.f;
    __syncthreads();
    if (d < 4) {
        int h = d;
        for (int j = 0; j < 32; j++) perm[h][j] = h * 32 + j;
        for (int i = 1; i < 32; i++) {
            int key = perm[h][i];
            float kt = t_s[key];
            int j = i - 1;
            while (j >= 0 && t_s[perm[h][j]] > kt) { perm[h][j + 1] = perm[h][j]; j--; }
            perm[h][j + 1] = key;
        }
    }
    __syncthreads();
    g_ts[d] = t_s[perm[d >> 5][d & 31]];

    const float* wrow = W1 + d * 128;
    float Call = 0.f, Qd = 0.f;
    for (int h = 0; h < 4; h++) {
        float Stot = 0.f, Ttot = 0.f, Ph = 0.f;
        for (int j = 0; j < 32; j++) {
            int c = perm[h][j];
            float w = wrow[c];
            float wa = w * au_s[c];
            Stot += wa;
            Ttot = fmaf(wa, t_s[c], Ttot);
            Call = fmaf(w, avb_s[c], Call);
            Ph = fmaf(w, u_s[c], Ph);
            Qd = fmaf(w, vb_s[c], Qd);
        }
        g_P[h * 128 + d] = Ph;
        float S = 0.f, T = 0.f;
        for (int k = 0; k <= 32; k++) {
            g_D1[(h * 33 + k) * 128 + d] = 2.f * S - Stot;
            g_D2[(h * 33 + k) * 128 + d] = 2.f * T - Ttot;
            if (k < 32) {
                int c = perm[h][k];
                float wa = wrow[c] * au_s[c];
                S += wa;
                T = fmaf(wa, t_s[c], T);
            }
        }
    }
    g_Q[d] = Qd;
    g_Cc[d] = Call;
}

// ---------------- layer-2 projection prep ----------------------------------------
__global__ void __launch_bounds__(512) k_proj(const float* __restrict__ W2,
                                              const float* __restrict__ al2,
                                              const float* __restrict__ ar2,
                                              const float* __restrict__ pW,
                                              const float* __restrict__ pb,
                                              const float* __restrict__ b2) {
    int tid = threadIdx.x;
    int h = tid >> 7, k = tid & 127;
    float sl = 0.f, sr = 0.f, sq = 0.f;
#pragma unroll 4
    for (int f = 0; f < 32; f++) {
        float w = W2[(h * 32 + f) * 128 + k];
        sl = fmaf(al2[h * 32 + f], w, sl);
        sr = fmaf(ar2[h * 32 + f], w, sr);
        sq = fmaf(pW[h * 32 + f], w, sq);
    }
    g_pl2[tid] = sl;
    g_pr2[tid] = sr;
    g_q[tid] = sq;
    if (tid == 0) {
        float c = pb[0];
        for (int cc = 0; cc < 128; cc++) c = fmaf(pW[cc], b2[cc], c);
        g_c0[0] = c;
    }
}

// ---------------- layer-0 aggregation --------------------------------------------
__global__ void __launch_bounds__(256) k_agg0(const float* __restrict__ w) {
    int gw = (blockIdx.x * blockDim.x + threadIdx.x) >> 5;
    int lane = threadIdx.x & 31;
    if (gw >= NN) return;
    int n = gw;
    int beg = g_rowptr[n], end = g_rowptr[n + 1];

    float CL0 = g_sc[0], CL1 = g_sc[1], CL2 = g_sc[2], CL3 = g_sc[3];
    float DL0 = g_sc[4], DL1 = g_sc[5], DL2 = g_sc[6], DL3 = g_sc[7];
    float wn = w[n];
    float er0 = fmaf(wn, g_sc[8],  g_sc[12]);
    float er1 = fmaf(wn, g_sc[9],  g_sc[13]);
    float er2 = fmaf(wn, g_sc[10], g_sc[14]);
    float er3 = fmaf(wn, g_sc[11], g_sc[15]);

    float wmax = funord(g_wmm[0]), wmin = funord(g_wmm[1]);
    float m0 = fmaf(CL0 >= 0.f ? wmax : wmin, CL0, DL0) + er0; m0 = m0 >= 0.f ? m0 : 0.2f * m0;
    float m1 = fmaf(CL1 >= 0.f ? wmax : wmin, CL1, DL1) + er1; m1 = m1 >= 0.f ? m1 : 0.2f * m1;
    float m2 = fmaf(CL2 >= 0.f ? wmax : wmin, CL2, DL2) + er2; m2 = m2 >= 0.f ? m2 : 0.2f * m2;
    float m3 = fmaf(CL3 >= 0.f ? wmax : wmin, CL3, DL3) + er3; m3 = m3 >= 0.f ? m3 : 0.2f * m3;

    float S0 = 0.f, S1 = 0.f, S2 = 0.f, S3 = 0.f;
    float T0 = 0.f, T1 = 0.f, T2 = 0.f, T3 = 0.f;
    for (int j = beg + lane; j < end; j += 32) {
        float ws = w[g_csr[j]];
        float e0 = fmaf(ws, CL0, DL0) + er0; e0 = e0 >= 0.f ? e0 : 0.2f * e0;
        float e1 = fmaf(ws, CL1, DL1) + er1; e1 = e1 >= 0.f ? e1 : 0.2f * e1;
        float e2 = fmaf(ws, CL2, DL2) + er2; e2 = e2 >= 0.f ? e2 : 0.2f * e2;
        float e3 = fmaf(ws, CL3, DL3) + er3; e3 = e3 >= 0.f ? e3 : 0.2f * e3;
        float p0 = __expf(e0 - m0), p1 = __expf(e1 - m1);
        float p2 = __expf(e2 - m2), p3 = __expf(e3 - m3);
        S0 += p0; S1 += p1; S2 += p2; S3 += p3;
        T0 = fmaf(p0, ws, T0); T1 = fmaf(p1, ws, T1);
        T2 = fmaf(p2, ws, T2); T3 = fmaf(p3, ws, T3);
    }
#pragma unroll
    for (int o = 16; o > 0; o >>= 1) {
        S0 += __shfl_xor_sync(0xffffffffu, S0, o);
        S1 += __shfl_xor_sync(0xffffffffu, S1, o);
        S2 += __shfl_xor_sync(0xffffffffu, S2, o);
        S3 += __shfl_xor_sync(0xffffffffu, S3, o);
        T0 += __shfl_xor_sync(0xffffffffu, T0, o);
        T1 += __shfl_xor_sync(0xffffffffu, T1, o);
        T2 += __shfl_xor_sync(0xffffffffu, T2, o);
        T3 += __shfl_xor_sync(0xffffffffu, T3, o);
    }
    if (lane == 0)
        g_T[n] = make_float4(T0 / S0, T1 / S1, T2 / S2, T3 / S3);
}

// ---------------- layer-1 h1 via piecewise-linear evaluation (replaces GEMM) ----
__global__ void __launch_bounds__(256) k_pw(const float* __restrict__ al,
                                            const float* __restrict__ ar) {
    __shared__ float sP[512], sQ[128], sC[128], sts[128];
    __shared__ unsigned selmax[4];
    int tid = threadIdx.x;
    if (tid < 4) selmax[tid] = 0u;
    sP[tid] = g_P[tid];
    sP[tid + 256] = g_P[tid + 256];
    if (tid < 128) {
        sQ[tid] = g_Q[tid];
        sC[tid] = g_Cc[tid];
        sts[tid] = g_ts[tid];
    }
    __syncthreads();

    int gw = (blockIdx.x * 256 + tid) >> 5;
    int lane = tid & 31;
    if (gw < NN) {
        float4 Av = g_T[gw];
        float Ah[4] = {Av.x, Av.y, Av.z, Av.w};
        int kh[4];
#pragma unroll
        for (int h = 0; h < 4; h++) {
            const float* ts = sts + h * 32;
            float A = Ah[h];
            int k = 0;
            if (ts[15] < A) k = 16;
            if (ts[k + 7] < A) k += 8;
            if (ts[k + 3] < A) k += 4;
            if (ts[k + 1] < A) k += 2;
            if (ts[k] < A) k += 1;
            if (k == 31 && ts[31] < A) k = 32;   // 6th step: rank can be 32
            kh[h] = k;
        }
        int c0 = lane * 4;
        float l0 = sQ[c0], l1 = sQ[c0 + 1], l2 = sQ[c0 + 2], l3 = sQ[c0 + 3];
        float b0 = sC[c0], b1 = sC[c0 + 1], b2 = sC[c0 + 2], b3 = sC[c0 + 3];
#pragma unroll
        for (int h = 0; h < 4; h++) {
            float A = Ah[h];
            const float* Pp = sP + h * 128 + c0;
            l0 = fmaf(A, Pp[0], l0); l1 = fmaf(A, Pp[1], l1);
            l2 = fmaf(A, Pp[2], l2); l3 = fmaf(A, Pp[3], l3);
            int off = (h * 33 + kh[h]) * 128 + c0;
            float4 D1 = *(const float4*)&g_D1[off];
            float4 D2 = *(const float4*)&g_D2[off];
            b0 = fmaf(A, D1.x, b0) - D2.x;
            b1 = fmaf(A, D1.y, b1) - D2.y;
            b2 = fmaf(A, D1.z, b2) - D2.z;
            b3 = fmaf(A, D1.w, b3) - D2.w;
        }
        float h0 = 0.505f * l0 + 0.495f * b0;
        float h1v = 0.505f * l1 + 0.495f * b1;
        float h2v = 0.505f * l2 + 0.495f * b2;
        float h3v = 0.505f * l3 + 0.495f * b3;
        *(float4*)&g_h[(size_t)gw * 128 + c0] = make_float4(h0, h1v, h2v, h3v);

        float4 alv = *(const float4*)&al[c0];
        float4 arv = *(const float4*)&ar[c0];
        float pl = h0 * alv.x + h1v * alv.y + h2v * alv.z + h3v * alv.w;
        float pr = h0 * arv.x + h1v * arv.y + h2v * arv.z + h3v * arv.w;
#pragma unroll
        for (int o = 4; o > 0; o >>= 1) {
            pl += __shfl_xor_sync(0xffffffffu, pl, o);
            pr += __shfl_xor_sync(0xffffffffu, pr, o);
        }
        if ((lane & 7) == 0) {
            int hh = lane >> 3;
            g_el[gw * 4 + hh] = pl;
            g_er[gw * 4 + hh] = pr;
            atomicMax(&selmax[hh], ford(pl));
        }
    }
    __syncthreads();
    if (tid < 4 && selmax[tid]) atomicMax(&g_elmax[tid], selmax[tid]);
}

// ---------------- layer-1 aggregation: y2 = leaky(sum alpha h1 + b1, 0.01) ------
__device__ __forceinline__ float sel4(float4 v, int hh) {
    return (hh & 2) ? ((hh & 1) ? v.w : v.z) : ((hh & 1) ? v.y : v.x);
}

__global__ void __launch_bounds__(256) k_agg1(const float* __restrict__ bias) {
    int gw = (blockIdx.x * blockDim.x + threadIdx.x) >> 5;
    int lane = threadIdx.x & 31;
    if (gw >= NN) return;
    int n = gw;
    int beg = g_rowptr[n], end = g_rowptr[n + 1];
    float4 er4 = *(const float4*)&g_er[n * 4];

    int hh = lane >> 3;
    float erh = sel4(er4, hh);
    float mh = funord(g_elmax[hh]) + erh;
    mh = mh >= 0.f ? mh : 0.2f * mh;

    float a0 = 0.f, a1 = 0.f, a2 = 0.f, a3 = 0.f, sacc = 0.f;
    for (int j = beg; j < end; j++) {
        int s = g_csr[j];
        float4 el4 = *(const float4*)&g_el[s * 4];
        float e = sel4(el4, hh) + erh;
        e = e >= 0.f ? e : 0.2f * e;
        float p = __expf(e - mh);
        float4 hv = *(const float4*)&g_h[s * 128 + lane * 4];
        a0 = fmaf(p, hv.x, a0); a1 = fmaf(p, hv.y, a1);
        a2 = fmaf(p, hv.z, a2); a3 = fmaf(p, hv.w, a3);
        sacc += p;
    }
    float inv = 1.f / sacc;
    int col = lane * 4;
    float4 bv = *(const float4*)&bias[col];
    float ox = fmaf(a0, inv, bv.x), oy = fmaf(a1, inv, bv.y);
    float oz = fmaf(a2, inv, bv.z), ow = fmaf(a3, inv, bv.w);
    ox = ox >= 0.f ? ox : 0.01f * ox;
    oy = oy >= 0.f ? oy : 0.01f * oy;
    oz = oz >= 0.f ? oz : 0.01f * oz;
    ow = ow >= 0.f ? ow : 0.01f * ow;
    *(float4*)&g_x0[n * 128 + col] = make_float4(ox, oy, oz, ow);
}

// ---------------- layer-2 attention ---------------------------------------------
__global__ void __launch_bounds__(256) k_att2() {
    __shared__ float spl[512], spr[512];
    __shared__ unsigned selmax[4];
    int tid = threadIdx.x;
    if (tid < 4) selmax[tid] = 0u;
    spl[tid] = g_pl2[tid];       spl[tid + 256] = g_pl2[tid + 256];
    spr[tid] = g_pr2[tid];       spr[tid + 256] = g_pr2[tid + 256];
    __syncthreads();

    int gw = (blockIdx.x * 256 + tid) >> 5;
    int lane = tid & 31;
    if (gw < NN) {
        int c = lane * 4;
        float4 y = *(const float4*)&g_x0[gw * 128 + c];
        float el[4], er[4];
#pragma unroll
        for (int h = 0; h < 4; h++) {
            const float* pl = spl + h * 128 + c;
            const float* pr = spr + h * 128 + c;
            el[h] = y.x * pl[0] + y.y * pl[1] + y.z * pl[2] + y.w * pl[3];
            er[h] = y.x * pr[0] + y.y * pr[1] + y.z * pr[2] + y.w * pr[3];
        }
#pragma unroll
        for (int o = 16; o > 0; o >>= 1) {
#pragma unroll
            for (int h = 0; h < 4; h++) {
                el[h] += __shfl_xor_sync(0xffffffffu, el[h], o);
                er[h] += __shfl_xor_sync(0xffffffffu, er[h], o);
            }
        }
        if (lane == 0) {
            *(float4*)&g_el[gw * 4] = make_float4(el[0], el[1], el[2], el[3]);
            *(float4*)&g_er[gw * 4] = make_float4(er[0], er[1], er[2], er[3]);
#pragma unroll
            for (int h = 0; h < 4; h++) atomicMax(&selmax[h], ford(el[h]));
        }
    }
    __syncthreads();
    if (tid < 4 && selmax[tid]) atomicMax(&g_elmax[4 + tid], selmax[tid]);
}

// ---------------- final fused aggregation + prediction --------------------------
__global__ void __launch_bounds__(256) k_aggF(float* __restrict__ out) {
    __shared__ float sq[512];
    int tid = threadIdx.x;
    sq[tid] = g_q[tid];
    sq[tid + 256] = g_q[tid + 256];
    __syncthreads();

    int gw = (blockIdx.x * 256 + tid) >> 5;
    int lane = tid & 31;
    if (gw >= NN) return;
    int n = gw;
    int beg = g_rowptr[n], end = g_rowptr[n + 1];
    float4 er4 = *(const float4*)&g_er[n * 4];

    int c = lane * 4;
    float q0x = sq[c],       q0y = sq[c + 1],   q0z = sq[c + 2],   q0w = sq[c + 3];
    float q1x = sq[128 + c], q1y = sq[129 + c], q1z = sq[130 + c], q1w = sq[131 + c];
    float q2x = sq[256 + c], q2y = sq[257 + c], q2z = sq[258 + c], q2w = sq[259 + c];
    float q3x = sq[384 + c], q3y = sq[385 + c], q3z = sq[386 + c], q3w = sq[387 + c];

    float m0 = funord(g_elmax[4]) + er4.x; m0 = m0 >= 0.f ? m0 : 0.2f * m0;
    float m1 = funord(g_elmax[5]) + er4.y; m1 = m1 >= 0.f ? m1 : 0.2f * m1;
    float m2 = funord(g_elmax[6]) + er4.z; m2 = m2 >= 0.f ? m2 : 0.2f * m2;
    float m3 = funord(g_elmax[7]) + er4.w; m3 = m3 >= 0.f ? m3 : 0.2f * m3;

    float t0 = 0.f, t1 = 0.f, t2 = 0.f, t3 = 0.f;
    float S0 = 0.f, S1 = 0.f, S2 = 0.f, S3 = 0.f;
    for (int j = beg; j < end; j++) {
        int s = g_csr[j];
        float4 el4 = *(const float4*)&g_el[s * 4];
        float e0 = el4.x + er4.x; e0 = e0 >= 0.f ? e0 : 0.2f * e0;
        float e1 = el4.y + er4.y; e1 = e1 >= 0.f ? e1 : 0.2f * e1;
        float e2 = el4.z + er4.z; e2 = e2 >= 0.f ? e2 : 0.2f * e2;
        float e3 = el4.w + er4.w; e3 = e3 >= 0.f ? e3 : 0.2f * e3;
        float p0 = __expf(e0 - m0), p1 = __expf(e1 - m1);
        float p2 = __expf(e2 - m2), p3 = __expf(e3 - m3);
        float4 y = *(const float4*)&g_x0[(size_t)s * 128 + c];
        t0 = fmaf(p0, y.x * q0x + y.y * q0y + y.z * q0z + y.w * q0w, t0);
        t1 = fmaf(p1, y.x * q1x + y.y * q1y + y.z * q1z + y.w * q1w, t1);
        t2 = fmaf(p2, y.x * q2x + y.y * q2y + y.z * q2z + y.w * q2w, t2);
        t3 = fmaf(p3, y.x * q3x + y.y * q3y + y.z * q3z + y.w * q3w, t3);
        S0 += p0; S1 += p1; S2 += p2; S3 += p3;
    }
    float t = t0 / S0 + t1 / S1 + t2 / S2 + t3 / S3;
#pragma unroll
    for (int o = 16; o > 0; o >>= 1) t += __shfl_xor_sync(0xffffffffu, t, o);
    if (lane == 0) out[n] = t + g_c0[0];
}

// ---------------- launch --------------------------------------------------------
extern "C" void kernel_launch(void* const* d_in, const int* in_sizes, int n_in,
                              void* d_out, int out_size) {
    const float* weights = (const float*)d_in[0];
    const float* linW    = (const float*)d_in[1];
    const float* linb    = (const float*)d_in[2];
    const float* fcW     = (const float*)d_in[3];
    const float* al      = (const float*)d_in[4];
    const float* ar      = (const float*)d_in[5];
    const float* cb      = (const float*)d_in[6];
    const float* pW      = (const float*)d_in[7];
    const float* pb      = (const float*)d_in[8];
    const int*   src     = (const int*)d_in[9];
    const int*   dst     = (const int*)d_in[10];
    float* out = (float*)d_out;

    void* p = nullptr;
    cudaGetSymbolAddress(&p, g_cnt);
    cudaMemsetAsync(p, 0, NN * sizeof(int));
    cudaGetSymbolAddress(&p, g_elmax);
    cudaMemsetAsync(p, 0, 8 * sizeof(unsigned));
    cudaGetSymbolAddress(&p, g_wmm);
    cudaMemsetAsync(p, 0x00, sizeof(unsigned));
    cudaMemsetAsync((char*)p + sizeof(unsigned), 0xFF, sizeof(unsigned));

    k_hist<<<(EE + 255) / 256, 256>>>(dst);
    k_scanA<<<SCAN_B, 1024>>>();
    k_scanB<<<1, 128>>>();
    k_scanC<<<SCAN_B, 1024>>>();
    k_scatter<<<(EE + NN + 255) / 256, 256>>>(src, dst);

    k_wmm<<<(NN + 255) / 256, 256>>>(weights);
    k_prep<<<1, 1024>>>(fcW, linW, linb, al, ar, cb);
    k_prep2<<<1, 128>>>(fcW + DD * DD);
    k_proj<<<1, 512>>>(fcW + 2 * DD * DD, al + 2 * DD, ar + 2 * DD, pW, pb, cb + 2 * DD);

    const int AB = (NN * 32 + 255) / 256;

    k_agg0<<<AB, 256>>>(weights);
    k_pw<<<AB, 256>>>(al + DD, ar + DD);
    k_agg1<<<AB, 256>>>(cb + DD);
    k_att2<<<AB, 256>>>();
    k_aggF<<<AB, 256>>>(out);
}

// round 15
// speedup vs baseline: 1.8050x; 1.3532x over previous
#include <cuda_runtime.h>
#include <math.h>
#include <cstdint>

#define NN 100000
#define EE 600000
#define DD 128
#define ETOT (EE + NN)
#define SCAN_B ((NN + 1023) / 1024)   // 98

// ---------------- scratch (static device globals; no allocation) ----------------
__device__ float    g_x0[NN * DD];    // y2 = leaky(out1)
__device__ float    g_h [NN * DD];    // h1
__device__ float    g_el[NN * 4];
__device__ float    g_er[NN * 4];
__device__ float4   g_T [NN];
__device__ float4   g_z [NN];         // z[n][h] = q_h . y2[n]
__device__ float    g_u [DD];
__device__ float    g_vb[DD];
__device__ float    g_sc[16];
__device__ float    g_pl2[512];
__device__ float    g_pr2[512];
__device__ float    g_q  [512];
__device__ float    g_c0[1];
// piecewise-linear layer-1 tables
__device__ float    g_D1[4 * 33 * 128];
__device__ float    g_D2[4 * 33 * 128];
__device__ float    g_P [4 * 128];
__device__ float    g_Q [128];
__device__ float    g_Cc[128];
__device__ float    g_ts[128];        // [h][32] sorted breakpoints
__device__ unsigned g_elmax[8];
__device__ unsigned g_wmm[2];
__device__ int      g_rowptr[NN + 1];
__device__ int      g_cnt[NN];
__device__ int      g_ps [NN];
__device__ int      g_bsum[SCAN_B];
__device__ int      g_boff[SCAN_B];
__device__ int      g_csr[ETOT];

__device__ __forceinline__ unsigned ford(float f) {
    unsigned u = __float_as_uint(f);
    return (u & 0x80000000u) ? ~u : (u | 0x80000000u);
}
__device__ __forceinline__ float funord(unsigned o) {
    return __uint_as_float((o & 0x80000000u) ? (o ^ 0x80000000u) : ~o);
}

// ---------------- CSR build ------------------------------------------------------
__global__ void k_hist(const int* __restrict__ dst) {
    int i = blockIdx.x * blockDim.x + threadIdx.x;
    if (i < EE) atomicAdd(&g_cnt[dst[i]], 1);
}

__global__ void __launch_bounds__(1024) k_scanA() {
    __shared__ int wsum[32];
    int tid = threadIdx.x, lane = tid & 31, warp = tid >> 5;
    int i = blockIdx.x * 1024 + tid;
    int c = (i < NN) ? g_cnt[i] + 1 : 0;
    int v = c;
#pragma unroll
    for (int o = 1; o < 32; o <<= 1) {
        int t = __shfl_up_sync(0xffffffffu, v, o);
        if (lane >= o) v += t;
    }
    if (lane == 31) wsum[warp] = v;
    __syncthreads();
    if (warp == 0) {
        int w = wsum[lane];
#pragma unroll
        for (int o = 1; o < 32; o <<= 1) {
            int t = __shfl_up_sync(0xffffffffu, w, o);
            if (lane >= o) w += t;
        }
        wsum[lane] = w;
    }
    __syncthreads();
    int incl = v + (warp > 0 ? wsum[warp - 1] : 0);
    if (i < NN) g_ps[i] = incl;
    if (tid == 1023) g_bsum[blockIdx.x] = incl;
}

__global__ void k_scanB() {
    __shared__ int wsum[4];
    int tid = threadIdx.x, lane = tid & 31, warp = tid >> 5;
    int s = (tid < SCAN_B) ? g_bsum[tid] : 0;
    int v = s;
#pragma unroll
    for (int o = 1; o < 32; o <<= 1) {
        int t = __shfl_up_sync(0xffffffffu, v, o);
        if (lane >= o) v += t;
    }
    if (lane == 31) wsum[warp] = v;
    __syncthreads();
    int base = 0;
    for (int w = 0; w < warp; w++) base += wsum[w];
    int incl = v + base;
    if (tid < SCAN_B) g_boff[tid] = incl - s;
    if (tid == 127) g_rowptr[NN] = incl;
}

__global__ void __launch_bounds__(1024) k_scanC() {
    int i = blockIdx.x * 1024 + threadIdx.x;
    if (i < NN) {
        int c = g_cnt[i] + 1;
        int e = g_ps[i] - c + g_boff[blockIdx.x];
        g_rowptr[i] = e;
        g_cnt[i] = e;
    }
}

__global__ void k_scatter(const int* __restrict__ src, const int* __restrict__ dst) {
    int i = blockIdx.x * blockDim.x + threadIdx.x;
    if (i < EE) {
        int p = atomicAdd(&g_cnt[dst[i]], 1);
        g_csr[p] = src[i];
    } else if (i < EE + NN) {
        int n = i - EE;
        int p = atomicAdd(&g_cnt[n], 1);
        g_csr[p] = n;
    }
}

// ---------------- global weight min/max ------------------------------------------
__global__ void __launch_bounds__(256) k_wmm(const float* __restrict__ w) {
    int i = blockIdx.x * blockDim.x + threadIdx.x;
    float v = (i < NN) ? w[i] : w[0];
    float mx = v, mn = v;
#pragma unroll
    for (int o = 16; o > 0; o >>= 1) {
        mx = fmaxf(mx, __shfl_xor_sync(0xffffffffu, mx, o));
        mn = fminf(mn, __shfl_xor_sync(0xffffffffu, mn, o));
    }
    if ((threadIdx.x & 31) == 0) {
        atomicMax(&g_wmm[0], ford(mx));
        atomicMin(&g_wmm[1], ford(mn));
    }
}

// ---------------- layer-0 analytic prep ------------------------------------------
__global__ void __launch_bounds__(1024) k_prep(const float* __restrict__ fcW,
                                               const float* __restrict__ linW,
                                               const float* __restrict__ linb,
                                               const float* __restrict__ al,
                                               const float* __restrict__ ar,
                                               const float* __restrict__ cb) {
    __shared__ float su[128], sv[128];
    int tid = threadIdx.x;
    int d = tid >> 3, s = tid & 7;
    float uu = 0.f, vv = 0.f;
#pragma unroll
    for (int q = 0; q < 4; q++) {
        int k = s * 16 + q * 4;
        float4 w = *(const float4*)&fcW[d * 128 + k];
        float4 lw = *(const float4*)&linW[k];
        float4 lb = *(const float4*)&linb[k];
        uu = fmaf(w.x, lw.x, fmaf(w.y, lw.y, fmaf(w.z, lw.z, fmaf(w.w, lw.w, uu))));
        vv = fmaf(w.x, lb.x, fmaf(w.y, lb.y, fmaf(w.z, lb.z, fmaf(w.w, lb.w, vv))));
    }
#pragma unroll
    for (int o = 1; o <= 4; o <<= 1) {
        uu += __shfl_xor_sync(0xffffffffu, uu, o);
        vv += __shfl_xor_sync(0xffffffffu, vv, o);
    }
    if (s == 0) {
        su[d] = uu;
        sv[d] = vv;
        g_u[d] = uu;
        g_vb[d] = vv + cb[d];
    }
    __syncthreads();
    if (tid < 16) {
        int type = tid >> 2, h = tid & 3;
        const float* a = (type < 2) ? al : ar;
        const float* base = (type & 1) ? sv : su;
        float x = 0.f;
        for (int f = 0; f < 32; f++) x = fmaf(base[h * 32 + f], a[h * 32 + f], x);
        g_sc[type * 4 + h] = x;
    }
}

// ---------------- layer-1 piecewise tables ---------------------------------------
__global__ void __launch_bounds__(128) k_prep2(const float* __restrict__ W1) {
    __shared__ float t_s[128], au_s[128], avb_s[128], u_s[128], vb_s[128];
    __shared__ int perm[4][32];
    int d = threadIdx.x;
    float u = g_u[d], vb = g_vb[d];
    float au = fabsf(u);
    int z = (au < 1e-30f);
    u_s[d] = u;
    vb_s[d] = vb;
    t_s[d] = z ? 0.f : (-vb / u);
    au_s[d] = z ? 0.f : au;
    avb_s[d] = z ? fabsf(vb) : 0.f;
    __syncthreads();
    if (d < 4) {
        int h = d;
        for (int j = 0; j < 32; j++) perm[h][j] = h * 32 + j;
        for (int i = 1; i < 32; i++) {
            int key = perm[h][i];
            float kt = t_s[key];
            int j = i - 1;
            while (j >= 0 && t_s[perm[h][j]] > kt) { perm[h][j + 1] = perm[h][j]; j--; }
            perm[h][j + 1] = key;
        }
    }
    __syncthreads();
    g_ts[d] = t_s[perm[d >> 5][d & 31]];

    const float* wrow = W1 + d * 128;
    float Call = 0.f, Qd = 0.f;
    for (int h = 0; h < 4; h++) {
        float Stot = 0.f, Ttot = 0.f, Ph = 0.f;
        for (int j = 0; j < 32; j++) {
            int c = perm[h][j];
            float w = wrow[c];
            float wa = w * au_s[c];
            Stot += wa;
            Ttot = fmaf(wa, t_s[c], Ttot);
            Call = fmaf(w, avb_s[c], Call);
            Ph = fmaf(w, u_s[c], Ph);
            Qd = fmaf(w, vb_s[c], Qd);
        }
        g_P[h * 128 + d] = Ph;
        float S = 0.f, T = 0.f;
        for (int k = 0; k <= 32; k++) {
            g_D1[(h * 33 + k) * 128 + d] = 2.f * S - Stot;
            g_D2[(h * 33 + k) * 128 + d] = 2.f * T - Ttot;
            if (k < 32) {
                int c = perm[h][k];
                float wa = wrow[c] * au_s[c];
                S += wa;
                T = fmaf(wa, t_s[c], T);
            }
        }
    }
    g_Q[d] = Qd;
    g_Cc[d] = Call;
}

// ---------------- layer-2 projection prep ----------------------------------------
__global__ void __launch_bounds__(512) k_proj(const float* __restrict__ W2,
                                              const float* __restrict__ al2,
                                              const float* __restrict__ ar2,
                                              const float* __restrict__ pW,
                                              const float* __restrict__ pb,
                                              const float* __restrict__ b2) {
    int tid = threadIdx.x;
    int h = tid >> 7, k = tid & 127;
    float sl = 0.f, sr = 0.f, sq = 0.f;
#pragma unroll 4
    for (int f = 0; f < 32; f++) {
        float w = W2[(h * 32 + f) * 128 + k];
        sl = fmaf(al2[h * 32 + f], w, sl);
        sr = fmaf(ar2[h * 32 + f], w, sr);
        sq = fmaf(pW[h * 32 + f], w, sq);
    }
    g_pl2[tid] = sl;
    g_pr2[tid] = sr;
    g_q[tid] = sq;
    if (tid == 0) {
        float c = pb[0];
        for (int cc = 0; cc < 128; cc++) c = fmaf(pW[cc], b2[cc], c);
        g_c0[0] = c;
    }
}

// ---------------- layer-0 aggregation: one THREAD per node -----------------------
__global__ void __launch_bounds__(256) k_agg0(const float* __restrict__ w) {
    int n = blockIdx.x * blockDim.x + threadIdx.x;
    if (n >= NN) return;
    int beg = g_rowptr[n], end = g_rowptr[n + 1];

    float CL0 = g_sc[0], CL1 = g_sc[1], CL2 = g_sc[2], CL3 = g_sc[3];
    float DL0 = g_sc[4], DL1 = g_sc[5], DL2 = g_sc[6], DL3 = g_sc[7];
    float wn = w[n];
    float er0 = fmaf(wn, g_sc[8],  g_sc[12]);
    float er1 = fmaf(wn, g_sc[9],  g_sc[13]);
    float er2 = fmaf(wn, g_sc[10], g_sc[14]);
    float er3 = fmaf(wn, g_sc[11], g_sc[15]);

    float wmax = funord(g_wmm[0]), wmin = funord(g_wmm[1]);
    float m0 = fmaf(CL0 >= 0.f ? wmax : wmin, CL0, DL0) + er0; m0 = m0 >= 0.f ? m0 : 0.2f * m0;
    float m1 = fmaf(CL1 >= 0.f ? wmax : wmin, CL1, DL1) + er1; m1 = m1 >= 0.f ? m1 : 0.2f * m1;
    float m2 = fmaf(CL2 >= 0.f ? wmax : wmin, CL2, DL2) + er2; m2 = m2 >= 0.f ? m2 : 0.2f * m2;
    float m3 = fmaf(CL3 >= 0.f ? wmax : wmin, CL3, DL3) + er3; m3 = m3 >= 0.f ? m3 : 0.2f * m3;

    float S0 = 0.f, S1 = 0.f, S2 = 0.f, S3 = 0.f;
    float T0 = 0.f, T1 = 0.f, T2 = 0.f, T3 = 0.f;
    for (int j = beg; j < end; j++) {
        float ws = w[g_csr[j]];
        float e0 = fmaf(ws, CL0, DL0) + er0; e0 = e0 >= 0.f ? e0 : 0.2f * e0;
        float e1 = fmaf(ws, CL1, DL1) + er1; e1 = e1 >= 0.f ? e1 : 0.2f * e1;
        float e2 = fmaf(ws, CL2, DL2) + er2; e2 = e2 >= 0.f ? e2 : 0.2f * e2;
        float e3 = fmaf(ws, CL3, DL3) + er3; e3 = e3 >= 0.f ? e3 : 0.2f * e3;
        float p0 = __expf(e0 - m0), p1 = __expf(e1 - m1);
        float p2 = __expf(e2 - m2), p3 = __expf(e3 - m3);
        S0 += p0; S1 += p1; S2 += p2; S3 += p3;
        T0 = fmaf(p0, ws, T0); T1 = fmaf(p1, ws, T1);
        T2 = fmaf(p2, ws, T2); T3 = fmaf(p3, ws, T3);
    }
    g_T[n] = make_float4(T0 / S0, T1 / S1, T2 / S2, T3 / S3);
}

// ---------------- layer-1 h1 via piecewise-linear evaluation ---------------------
__global__ void __launch_bounds__(256) k_pw(const float* __restrict__ al,
                                            const float* __restrict__ ar) {
    __shared__ float sP[512], sQ[128], sC[128], sts[128];
    __shared__ unsigned selmax[4];
    int tid = threadIdx.x;
    if (tid < 4) selmax[tid] = 0u;
    sP[tid] = g_P[tid];
    sP[tid + 256] = g_P[tid + 256];
    if (tid < 128) {
        sQ[tid] = g_Q[tid];
        sC[tid] = g_Cc[tid];
        sts[tid] = g_ts[tid];
    }
    __syncthreads();

    int gw = (blockIdx.x * 256 + tid) >> 5;
    int lane = tid & 31;
    if (gw < NN) {
        float4 Av = g_T[gw];
        float Ah[4] = {Av.x, Av.y, Av.z, Av.w};
        int kh[4];
#pragma unroll
        for (int h = 0; h < 4; h++) {
            const float* ts = sts + h * 32;
            float A = Ah[h];
            int k = 0;
            if (ts[15] < A) k = 16;
            if (ts[k + 7] < A) k += 8;
            if (ts[k + 3] < A) k += 4;
            if (ts[k + 1] < A) k += 2;
            if (ts[k] < A) k += 1;
            if (k == 31 && ts[31] < A) k = 32;
            kh[h] = k;
        }
        int c0 = lane * 4;
        float l0 = sQ[c0], l1 = sQ[c0 + 1], l2 = sQ[c0 + 2], l3 = sQ[c0 + 3];
        float b0 = sC[c0], b1 = sC[c0 + 1], b2 = sC[c0 + 2], b3 = sC[c0 + 3];
#pragma unroll
        for (int h = 0; h < 4; h++) {
            float A = Ah[h];
            const float* Pp = sP + h * 128 + c0;
            l0 = fmaf(A, Pp[0], l0); l1 = fmaf(A, Pp[1], l1);
            l2 = fmaf(A, Pp[2], l2); l3 = fmaf(A, Pp[3], l3);
            int off = (h * 33 + kh[h]) * 128 + c0;
            float4 D1 = *(const float4*)&g_D1[off];
            float4 D2 = *(const float4*)&g_D2[off];
            b0 = fmaf(A, D1.x, b0) - D2.x;
            b1 = fmaf(A, D1.y, b1) - D2.y;
            b2 = fmaf(A, D1.z, b2) - D2.z;
            b3 = fmaf(A, D1.w, b3) - D2.w;
        }
        float h0 = 0.505f * l0 + 0.495f * b0;
        float h1v = 0.505f * l1 + 0.495f * b1;
        float h2v = 0.505f * l2 + 0.495f * b2;
        float h3v = 0.505f * l3 + 0.495f * b3;
        *(float4*)&g_h[(size_t)gw * 128 + c0] = make_float4(h0, h1v, h2v, h3v);

        float4 alv = *(const float4*)&al[c0];
        float4 arv = *(const float4*)&ar[c0];
        float pl = h0 * alv.x + h1v * alv.y + h2v * alv.z + h3v * alv.w;
        float pr = h0 * arv.x + h1v * arv.y + h2v * arv.z + h3v * arv.w;
#pragma unroll
        for (int o = 4; o > 0; o >>= 1) {
            pl += __shfl_xor_sync(0xffffffffu, pl, o);
            pr += __shfl_xor_sync(0xffffffffu, pr, o);
        }
        if ((lane & 7) == 0) {
            int hh = lane >> 3;
            g_el[gw * 4 + hh] = pl;
            g_er[gw * 4 + hh] = pr;
            atomicMax(&selmax[hh], ford(pl));
        }
    }
    __syncthreads();
    if (tid < 4 && selmax[tid]) atomicMax(&g_elmax[tid], selmax[tid]);
}

// ---------------- layer-1 aggregation (warp per node, h1 gather) ----------------
__device__ __forceinline__ float sel4(float4 v, int hh) {
    return (hh & 2) ? ((hh & 1) ? v.w : v.z) : ((hh & 1) ? v.y : v.x);
}

__global__ void __launch_bounds__(256) k_agg1(const float* __restrict__ bias) {
    int gw = (blockIdx.x * blockDim.x + threadIdx.x) >> 5;
    int lane = threadIdx.x & 31;
    if (gw >= NN) return;
    int n = gw;
    int beg = g_rowptr[n], end = g_rowptr[n + 1];
    float4 er4 = *(const float4*)&g_er[n * 4];

    int hh = lane >> 3;
    float erh = sel4(er4, hh);
    float mh = funord(g_elmax[hh]) + erh;
    mh = mh >= 0.f ? mh : 0.2f * mh;

    float a0 = 0.f, a1 = 0.f, a2 = 0.f, a3 = 0.f, sacc = 0.f;
    for (int j = beg; j < end; j++) {
        int s = g_csr[j];
        float4 el4 = *(const float4*)&g_el[s * 4];
        float e = sel4(el4, hh) + erh;
        e = e >= 0.f ? e : 0.2f * e;
        float p = __expf(e - mh);
        float4 hv = *(const float4*)&g_h[s * 128 + lane * 4];
        a0 = fmaf(p, hv.x, a0); a1 = fmaf(p, hv.y, a1);
        a2 = fmaf(p, hv.z, a2); a3 = fmaf(p, hv.w, a3);
        sacc += p;
    }
    float inv = 1.f / sacc;
    int col = lane * 4;
    float4 bv = *(const float4*)&bias[col];
    float ox = fmaf(a0, inv, bv.x), oy = fmaf(a1, inv, bv.y);
    float oz = fmaf(a2, inv, bv.z), ow = fmaf(a3, inv, bv.w);
    ox = ox >= 0.f ? ox : 0.01f * ox;
    oy = oy >= 0.f ? oy : 0.01f * oy;
    oz = oz >= 0.f ? oz : 0.01f * oz;
    ow = ow >= 0.f ? ow : 0.01f * ow;
    *(float4*)&g_x0[n * 128 + col] = make_float4(ox, oy, oz, ow);
}

// ---------------- layer-2 attention + z projection -------------------------------
__global__ void __launch_bounds__(256) k_att2() {
    __shared__ float spl[512], spr[512], sq[512];
    __shared__ unsigned selmax[4];
    int tid = threadIdx.x;
    if (tid < 4) selmax[tid] = 0u;
    spl[tid] = g_pl2[tid];       spl[tid + 256] = g_pl2[tid + 256];
    spr[tid] = g_pr2[tid];       spr[tid + 256] = g_pr2[tid + 256];
    sq[tid] = g_q[tid];          sq[tid + 256] = g_q[tid + 256];
    __syncthreads();

    int gw = (blockIdx.x * 256 + tid) >> 5;
    int lane = tid & 31;
    if (gw < NN) {
        int c = lane * 4;
        float4 y = *(const float4*)&g_x0[gw * 128 + c];
        float el[4], er[4], zz[4];
#pragma unroll
        for (int h = 0; h < 4; h++) {
            const float* pl = spl + h * 128 + c;
            const float* pr = spr + h * 128 + c;
            const float* qq = sq + h * 128 + c;
            el[h] = y.x * pl[0] + y.y * pl[1] + y.z * pl[2] + y.w * pl[3];
            er[h] = y.x * pr[0] + y.y * pr[1] + y.z * pr[2] + y.w * pr[3];
            zz[h] = y.x * qq[0] + y.y * qq[1] + y.z * qq[2] + y.w * qq[3];
        }
#pragma unroll
        for (int o = 16; o > 0; o >>= 1) {
#pragma unroll
            for (int h = 0; h < 4; h++) {
                el[h] += __shfl_xor_sync(0xffffffffu, el[h], o);
                er[h] += __shfl_xor_sync(0xffffffffu, er[h], o);
                zz[h] += __shfl_xor_sync(0xffffffffu, zz[h], o);
            }
        }
        if (lane == 0) {
            *(float4*)&g_el[gw * 4] = make_float4(el[0], el[1], el[2], el[3]);
            *(float4*)&g_er[gw * 4] = make_float4(er[0], er[1], er[2], er[3]);
            g_z[gw] = make_float4(zz[0], zz[1], zz[2], zz[3]);
#pragma unroll
            for (int h = 0; h < 4; h++) atomicMax(&selmax[h], ford(el[h]));
        }
    }
    __syncthreads();
    if (tid < 4 && selmax[tid]) atomicMax(&g_elmax[4 + tid], selmax[tid]);
}

// ---------------- final aggregation + prediction: one THREAD per node ------------
__global__ void __launch_bounds__(256) k_aggF(float* __restrict__ out) {
    int n = blockIdx.x * blockDim.x + threadIdx.x;
    if (n >= NN) return;
    int beg = g_rowptr[n], end = g_rowptr[n + 1];
    float4 er4 = *(const float4*)&g_er[n * 4];

    float m0 = funord(g_elmax[4]) + er4.x; m0 = m0 >= 0.f ? m0 : 0.2f * m0;
    float m1 = funord(g_elmax[5]) + er4.y; m1 = m1 >= 0.f ? m1 : 0.2f * m1;
    float m2 = funord(g_elmax[6]) + er4.z; m2 = m2 >= 0.f ? m2 : 0.2f * m2;
    float m3 = funord(g_elmax[7]) + er4.w; m3 = m3 >= 0.f ? m3 : 0.2f * m3;

    float t0 = 0.f, t1 = 0.f, t2 = 0.f, t3 = 0.f;
    float S0 = 0.f, S1 = 0.f, S2 = 0.f, S3 = 0.f;
    for (int j = beg; j < end; j++) {
        int s = g_csr[j];
        float4 el4 = *(const float4*)&g_el[s * 4];
        float4 z4 = g_z[s];
        float e0 = el4.x + er4.x; e0 = e0 >= 0.f ? e0 : 0.2f * e0;
        float e1 = el4.y + er4.y; e1 = e1 >= 0.f ? e1 : 0.2f * e1;
        float e2 = el4.z + er4.z; e2 = e2 >= 0.f ? e2 : 0.2f * e2;
        float e3 = el4.w + er4.w; e3 = e3 >= 0.f ? e3 : 0.2f * e3;
        float p0 = __expf(e0 - m0), p1 = __expf(e1 - m1);
        float p2 = __expf(e2 - m2), p3 = __expf(e3 - m3);
        t0 = fmaf(p0, z4.x, t0); t1 = fmaf(p1, z4.y, t1);
        t2 = fmaf(p2, z4.z, t2); t3 = fmaf(p3, z4.w, t3);
        S0 += p0; S1 += p1; S2 += p2; S3 += p3;
    }
    out[n] = t0 / S0 + t1 / S1 + t2 / S2 + t3 / S3 + g_c0[0];
}

// ---------------- launch --------------------------------------------------------
extern "C" void kernel_launch(void* const* d_in, const int* in_sizes, int n_in,
                              void* d_out, int out_size) {
    const float* weights = (const float*)d_in[0];
    const float* linW    = (const float*)d_in[1];
    const float* linb    = (const float*)d_in[2];
    const float* fcW     = (const float*)d_in[3];
    const float* al      = (const float*)d_in[4];
    const float* ar      = (const float*)d_in[5];
    const float* cb      = (const float*)d_in[6];
    const float* pW      = (const float*)d_in[7];
    const float* pb      = (const float*)d_in[8];
    const int*   src     = (const int*)d_in[9];
    const int*   dst     = (const int*)d_in[10];
    float* out = (float*)d_out;

    void* p = nullptr;
    cudaGetSymbolAddress(&p, g_cnt);
    cudaMemsetAsync(p, 0, NN * sizeof(int));
    cudaGetSymbolAddress(&p, g_elmax);
    cudaMemsetAsync(p, 0, 8 * sizeof(unsigned));
    cudaGetSymbolAddress(&p, g_wmm);
    cudaMemsetAsync(p, 0x00, sizeof(unsigned));
    cudaMemsetAsync((char*)p + sizeof(unsigned), 0xFF, sizeof(unsigned));

    k_hist<<<(EE + 255) / 256, 256>>>(dst);
    k_scanA<<<SCAN_B, 1024>>>();
    k_scanB<<<1, 128>>>();
    k_scanC<<<SCAN_B, 1024>>>();
    k_scatter<<<(EE + NN + 255) / 256, 256>>>(src, dst);

    k_wmm<<<(NN + 255) / 256, 256>>>(weights);
    k_prep<<<1, 1024>>>(fcW, linW, linb, al, ar, cb);
    k_prep2<<<1, 128>>>(fcW + DD * DD);
    k_proj<<<1, 512>>>(fcW + 2 * DD * DD, al + 2 * DD, ar + 2 * DD, pW, pb, cb + 2 * DD);

    const int AB  = (NN * 32 + 255) / 256;   // warp-per-node kernels
    const int AB1 = (NN + 255) / 256;        // thread-per-node kernels

    k_agg0<<<AB1, 256>>>(weights);
    k_pw<<<AB, 256>>>(al + DD, ar + DD);
    k_agg1<<<AB, 256>>>(cb + DD);
    k_att2<<<AB, 256>>>();
    k_aggF<<<AB1, 256>>>(out);
}

// round 16
// speedup vs baseline: 2.0254x; 1.1221x over previous
#include <cuda_runtime.h>
#include <cuda_fp16.h>
#include <math.h>
#include <cstdint>

#define NN 100000
#define EE 600000
#define DD 128
#define ETOT (EE + NN)
#define SCAN_B ((NN + 1023) / 1024)   // 98

// ---------------- scratch (static device globals; no allocation) ----------------
__device__ __half   g_h [NN * DD];    // h1 in fp16
__device__ float    g_el[NN * 4];     // layer-1 attn
__device__ float    g_er[NN * 4];
__device__ float4   g_el2[NN];        // layer-2 attn (separate: no overwrite hazard)
__device__ float4   g_er2[NN];
__device__ float4   g_T [NN];
__device__ float4   g_z [NN];         // z[n][h] = q_h . y2[n]
__device__ float    g_u [DD];
__device__ float    g_vb[DD];
__device__ float    g_sc[16];
__device__ float    g_pl2[512];
__device__ float    g_pr2[512];
__device__ float    g_q  [512];
__device__ float    g_c0[1];
// piecewise-linear layer-1 tables
__device__ float    g_D1[4 * 33 * 128];
__device__ float    g_D2[4 * 33 * 128];
__device__ float    g_P [4 * 128];
__device__ float    g_Q [128];
__device__ float    g_Cc[128];
__device__ float    g_ts[128];
__device__ unsigned g_elmax[8];
__device__ unsigned g_wmm[2];
__device__ int      g_rowptr[NN + 1];
__device__ int      g_cnt[NN];
__device__ int      g_ps [NN];
__device__ int      g_bsum[SCAN_B];
__device__ int      g_boff[SCAN_B];
__device__ int      g_csr[ETOT];

__device__ __forceinline__ unsigned ford(float f) {
    unsigned u = __float_as_uint(f);
    return (u & 0x80000000u) ? ~u : (u | 0x80000000u);
}
__device__ __forceinline__ float funord(unsigned o) {
    return __uint_as_float((o & 0x80000000u) ? (o ^ 0x80000000u) : ~o);
}

// ---------------- CSR build ------------------------------------------------------
__global__ void k_hist(const int* __restrict__ dst) {
    int i = blockIdx.x * blockDim.x + threadIdx.x;
    if (i < EE) atomicAdd(&g_cnt[dst[i]], 1);
}

__global__ void __launch_bounds__(1024) k_scanA() {
    __shared__ int wsum[32];
    int tid = threadIdx.x, lane = tid & 31, warp = tid >> 5;
    int i = blockIdx.x * 1024 + tid;
    int c = (i < NN) ? g_cnt[i] + 1 : 0;
    int v = c;
#pragma unroll
    for (int o = 1; o < 32; o <<= 1) {
        int t = __shfl_up_sync(0xffffffffu, v, o);
        if (lane >= o) v += t;
    }
    if (lane == 31) wsum[warp] = v;
    __syncthreads();
    if (warp == 0) {
        int w = wsum[lane];
#pragma unroll
        for (int o = 1; o < 32; o <<= 1) {
            int t = __shfl_up_sync(0xffffffffu, w, o);
            if (lane >= o) w += t;
        }
        wsum[lane] = w;
    }
    __syncthreads();
    int incl = v + (warp > 0 ? wsum[warp - 1] : 0);
    if (i < NN) g_ps[i] = incl;
    if (tid == 1023) g_bsum[blockIdx.x] = incl;
}

__global__ void k_scanB() {
    __shared__ int wsum[4];
    int tid = threadIdx.x, lane = tid & 31, warp = tid >> 5;
    int s = (tid < SCAN_B) ? g_bsum[tid] : 0;
    int v = s;
#pragma unroll
    for (int o = 1; o < 32; o <<= 1) {
        int t = __shfl_up_sync(0xffffffffu, v, o);
        if (lane >= o) v += t;
    }
    if (lane == 31) wsum[warp] = v;
    __syncthreads();
    int base = 0;
    for (int w = 0; w < warp; w++) base += wsum[w];
    int incl = v + base;
    if (tid < SCAN_B) g_boff[tid] = incl - s;
    if (tid == 127) g_rowptr[NN] = incl;
}

__global__ void __launch_bounds__(1024) k_scanC() {
    int i = blockIdx.x * 1024 + threadIdx.x;
    if (i < NN) {
        int c = g_cnt[i] + 1;
        int e = g_ps[i] - c + g_boff[blockIdx.x];
        g_rowptr[i] = e;
        g_cnt[i] = e;
    }
}

__global__ void k_scatter(const int* __restrict__ src, const int* __restrict__ dst) {
    int i = blockIdx.x * blockDim.x + threadIdx.x;
    if (i < EE) {
        int p = atomicAdd(&g_cnt[dst[i]], 1);
        g_csr[p] = src[i];
    } else if (i < EE + NN) {
        int n = i - EE;
        int p = atomicAdd(&g_cnt[n], 1);
        g_csr[p] = n;
    }
}

// ---------------- global weight min/max ------------------------------------------
__global__ void __launch_bounds__(256) k_wmm(const float* __restrict__ w) {
    int i = blockIdx.x * blockDim.x + threadIdx.x;
    float v = (i < NN) ? w[i] : w[0];
    float mx = v, mn = v;
#pragma unroll
    for (int o = 16; o > 0; o >>= 1) {
        mx = fmaxf(mx, __shfl_xor_sync(0xffffffffu, mx, o));
        mn = fminf(mn, __shfl_xor_sync(0xffffffffu, mn, o));
    }
    if ((threadIdx.x & 31) == 0) {
        atomicMax(&g_wmm[0], ford(mx));
        atomicMin(&g_wmm[1], ford(mn));
    }
}

// ---------------- layer-0 analytic prep ------------------------------------------
__global__ void __launch_bounds__(1024) k_prep(const float* __restrict__ fcW,
                                               const float* __restrict__ linW,
                                               const float* __restrict__ linb,
                                               const float* __restrict__ al,
                                               const float* __restrict__ ar,
                                               const float* __restrict__ cb) {
    __shared__ float su[128], sv[128];
    int tid = threadIdx.x;
    int d = tid >> 3, s = tid & 7;
    float uu = 0.f, vv = 0.f;
#pragma unroll
    for (int q = 0; q < 4; q++) {
        int k = s * 16 + q * 4;
        float4 w = *(const float4*)&fcW[d * 128 + k];
        float4 lw = *(const float4*)&linW[k];
        float4 lb = *(const float4*)&linb[k];
        uu = fmaf(w.x, lw.x, fmaf(w.y, lw.y, fmaf(w.z, lw.z, fmaf(w.w, lw.w, uu))));
        vv = fmaf(w.x, lb.x, fmaf(w.y, lb.y, fmaf(w.z, lb.z, fmaf(w.w, lb.w, vv))));
    }
#pragma unroll
    for (int o = 1; o <= 4; o <<= 1) {
        uu += __shfl_xor_sync(0xffffffffu, uu, o);
        vv += __shfl_xor_sync(0xffffffffu, vv, o);
    }
    if (s == 0) {
        su[d] = uu;
        sv[d] = vv;
        g_u[d] = uu;
        g_vb[d] = vv + cb[d];
    }
    __syncthreads();
    if (tid < 16) {
        int type = tid >> 2, h = tid & 3;
        const float* a = (type < 2) ? al : ar;
        const float* base = (type & 1) ? sv : su;
        float x = 0.f;
        for (int f = 0; f < 32; f++) x = fmaf(base[h * 32 + f], a[h * 32 + f], x);
        g_sc[type * 4 + h] = x;
    }
}

// ---------------- layer-1 piecewise tables ---------------------------------------
__global__ void __launch_bounds__(128) k_prep2(const float* __restrict__ W1) {
    __shared__ float t_s[128], au_s[128], avb_s[128], u_s[128], vb_s[128];
    __shared__ int perm[4][32];
    int d = threadIdx.x;
    float u = g_u[d], vb = g_vb[d];
    float au = fabsf(u);
    int z = (au < 1e-30f);
    u_s[d] = u;
    vb_s[d] = vb;
    t_s[d] = z ? 0.f : (-vb / u);
    au_s[d] = z ? 0.f : au;
    avb_s[d] = z ? fabsf(vb) : 0.f;
    __syncthreads();
    if (d < 4) {
        int h = d;
        for (int j = 0; j < 32; j++) perm[h][j] = h * 32 + j;
        for (int i = 1; i < 32; i++) {
            int key = perm[h][i];
            float kt = t_s[key];
            int j = i - 1;
            while (j >= 0 && t_s[perm[h][j]] > kt) { perm[h][j + 1] = perm[h][j]; j--; }
            perm[h][j + 1] = key;
        }
    }
    __syncthreads();
    g_ts[d] = t_s[perm[d >> 5][d & 31]];

    const float* wrow = W1 + d * 128;
    float Call = 0.f, Qd = 0.f;
    for (int h = 0; h < 4; h++) {
        float Stot = 0.f, Ttot = 0.f, Ph = 0.f;
        for (int j = 0; j < 32; j++) {
            int c = perm[h][j];
            float w = wrow[c];
            float wa = w * au_s[c];
            Stot += wa;
            Ttot = fmaf(wa, t_s[c], Ttot);
            Call = fmaf(w, avb_s[c], Call);
            Ph = fmaf(w, u_s[c], Ph);
            Qd = fmaf(w, vb_s[c], Qd);
        }
        g_P[h * 128 + d] = Ph;
        float S = 0.f, T = 0.f;
        for (int k = 0; k <= 32; k++) {
            g_D1[(h * 33 + k) * 128 + d] = 2.f * S - Stot;
            g_D2[(h * 33 + k) * 128 + d] = 2.f * T - Ttot;
            if (k < 32) {
                int c = perm[h][k];
                float wa = wrow[c] * au_s[c];
                S += wa;
                T = fmaf(wa, t_s[c], T);
            }
        }
    }
    g_Q[d] = Qd;
    g_Cc[d] = Call;
}

// ---------------- layer-2 projection prep ----------------------------------------
__global__ void __launch_bounds__(512) k_proj(const float* __restrict__ W2,
                                              const float* __restrict__ al2,
                                              const float* __restrict__ ar2,
                                              const float* __restrict__ pW,
                                              const float* __restrict__ pb,
                                              const float* __restrict__ b2) {
    int tid = threadIdx.x;
    int h = tid >> 7, k = tid & 127;
    float sl = 0.f, sr = 0.f, sq = 0.f;
#pragma unroll 4
    for (int f = 0; f < 32; f++) {
        float w = W2[(h * 32 + f) * 128 + k];
        sl = fmaf(al2[h * 32 + f], w, sl);
        sr = fmaf(ar2[h * 32 + f], w, sr);
        sq = fmaf(pW[h * 32 + f], w, sq);
    }
    g_pl2[tid] = sl;
    g_pr2[tid] = sr;
    g_q[tid] = sq;
    if (tid == 0) {
        float c = pb[0];
        for (int cc = 0; cc < 128; cc++) c = fmaf(pW[cc], b2[cc], c);
        g_c0[0] = c;
    }
}

// ---------------- layer-0 aggregation: one THREAD per node -----------------------
__global__ void __launch_bounds__(256) k_agg0(const float* __restrict__ w) {
    int n = blockIdx.x * blockDim.x + threadIdx.x;
    if (n >= NN) return;
    int beg = g_rowptr[n], end = g_rowptr[n + 1];

    float CL0 = g_sc[0], CL1 = g_sc[1], CL2 = g_sc[2], CL3 = g_sc[3];
    float DL0 = g_sc[4], DL1 = g_sc[5], DL2 = g_sc[6], DL3 = g_sc[7];
    float wn = w[n];
    float er0 = fmaf(wn, g_sc[8],  g_sc[12]);
    float er1 = fmaf(wn, g_sc[9],  g_sc[13]);
    float er2 = fmaf(wn, g_sc[10], g_sc[14]);
    float er3 = fmaf(wn, g_sc[11], g_sc[15]);

    float wmax = funord(g_wmm[0]), wmin = funord(g_wmm[1]);
    float m0 = fmaf(CL0 >= 0.f ? wmax : wmin, CL0, DL0) + er0; m0 = m0 >= 0.f ? m0 : 0.2f * m0;
    float m1 = fmaf(CL1 >= 0.f ? wmax : wmin, CL1, DL1) + er1; m1 = m1 >= 0.f ? m1 : 0.2f * m1;
    float m2 = fmaf(CL2 >= 0.f ? wmax : wmin, CL2, DL2) + er2; m2 = m2 >= 0.f ? m2 : 0.2f * m2;
    float m3 = fmaf(CL3 >= 0.f ? wmax : wmin, CL3, DL3) + er3; m3 = m3 >= 0.f ? m3 : 0.2f * m3;

    float S0 = 0.f, S1 = 0.f, S2 = 0.f, S3 = 0.f;
    float T0 = 0.f, T1 = 0.f, T2 = 0.f, T3 = 0.f;
    for (int j = beg; j < end; j++) {
        float ws = w[g_csr[j]];
        float e0 = fmaf(ws, CL0, DL0) + er0; e0 = e0 >= 0.f ? e0 : 0.2f * e0;
        float e1 = fmaf(ws, CL1, DL1) + er1; e1 = e1 >= 0.f ? e1 : 0.2f * e1;
        float e2 = fmaf(ws, CL2, DL2) + er2; e2 = e2 >= 0.f ? e2 : 0.2f * e2;
        float e3 = fmaf(ws, CL3, DL3) + er3; e3 = e3 >= 0.f ? e3 : 0.2f * e3;
        float p0 = __expf(e0 - m0), p1 = __expf(e1 - m1);
        float p2 = __expf(e2 - m2), p3 = __expf(e3 - m3);
        S0 += p0; S1 += p1; S2 += p2; S3 += p3;
        T0 = fmaf(p0, ws, T0); T1 = fmaf(p1, ws, T1);
        T2 = fmaf(p2, ws, T2); T3 = fmaf(p3, ws, T3);
    }
    g_T[n] = make_float4(T0 / S0, T1 / S1, T2 / S2, T3 / S3);
}

// ---------------- layer-1 h1 via piecewise-linear evaluation ---------------------
__global__ void __launch_bounds__(256) k_pw(const float* __restrict__ al,
                                            const float* __restrict__ ar) {
    __shared__ float sP[512], sQ[128], sC[128], sts[128];
    __shared__ unsigned selmax[4];
    int tid = threadIdx.x;
    if (tid < 4) selmax[tid] = 0u;
    sP[tid] = g_P[tid];
    sP[tid + 256] = g_P[tid + 256];
    if (tid < 128) {
        sQ[tid] = g_Q[tid];
        sC[tid] = g_Cc[tid];
        sts[tid] = g_ts[tid];
    }
    __syncthreads();

    int gw = (blockIdx.x * 256 + tid) >> 5;
    int lane = tid & 31;
    if (gw < NN) {
        float4 Av = g_T[gw];
        float Ah[4] = {Av.x, Av.y, Av.z, Av.w};
        int kh[4];
#pragma unroll
        for (int h = 0; h < 4; h++) {
            const float* ts = sts + h * 32;
            float A = Ah[h];
            int k = 0;
            if (ts[15] < A) k = 16;
            if (ts[k + 7] < A) k += 8;
            if (ts[k + 3] < A) k += 4;
            if (ts[k + 1] < A) k += 2;
            if (ts[k] < A) k += 1;
            if (k == 31 && ts[31] < A) k = 32;
            kh[h] = k;
        }
        int c0 = lane * 4;
        float l0 = sQ[c0], l1 = sQ[c0 + 1], l2 = sQ[c0 + 2], l3 = sQ[c0 + 3];
        float b0 = sC[c0], b1 = sC[c0 + 1], b2 = sC[c0 + 2], b3 = sC[c0 + 3];
#pragma unroll
        for (int h = 0; h < 4; h++) {
            float A = Ah[h];
            const float* Pp = sP + h * 128 + c0;
            l0 = fmaf(A, Pp[0], l0); l1 = fmaf(A, Pp[1], l1);
            l2 = fmaf(A, Pp[2], l2); l3 = fmaf(A, Pp[3], l3);
            int off = (h * 33 + kh[h]) * 128 + c0;
            float4 D1 = *(const float4*)&g_D1[off];
            float4 D2 = *(const float4*)&g_D2[off];
            b0 = fmaf(A, D1.x, b0) - D2.x;
            b1 = fmaf(A, D1.y, b1) - D2.y;
            b2 = fmaf(A, D1.z, b2) - D2.z;
            b3 = fmaf(A, D1.w, b3) - D2.w;
        }
        float h0 = 0.505f * l0 + 0.495f * b0;
        float h1v = 0.505f * l1 + 0.495f * b1;
        float h2v = 0.505f * l2 + 0.495f * b2;
        float h3v = 0.505f * l3 + 0.495f * b3;

        // store h1 as fp16 (4 halves = 8B per lane)
        __half2 hlo = __floats2half2_rn(h0, h1v);
        __half2 hhi = __floats2half2_rn(h2v, h3v);
        uint2 pk;
        pk.x = *(unsigned*)&hlo;
        pk.y = *(unsigned*)&hhi;
        *(uint2*)&g_h[(size_t)gw * 128 + c0] = pk;

        float4 alv = *(const float4*)&al[c0];
        float4 arv = *(const float4*)&ar[c0];
        float pl = h0 * alv.x + h1v * alv.y + h2v * alv.z + h3v * alv.w;
        float pr = h0 * arv.x + h1v * arv.y + h2v * arv.z + h3v * arv.w;
#pragma unroll
        for (int o = 4; o > 0; o >>= 1) {
            pl += __shfl_xor_sync(0xffffffffu, pl, o);
            pr += __shfl_xor_sync(0xffffffffu, pr, o);
        }
        if ((lane & 7) == 0) {
            int hh = lane >> 3;
            g_el[gw * 4 + hh] = pl;
            g_er[gw * 4 + hh] = pr;
            atomicMax(&selmax[hh], ford(pl));
        }
    }
    __syncthreads();
    if (tid < 4 && selmax[tid]) atomicMax(&g_elmax[tid], selmax[tid]);
}

// ---------------- fused layer-1 aggregation + layer-2 attention + z --------------
__device__ __forceinline__ float sel4(float4 v, int hh) {
    return (hh & 2) ? ((hh & 1) ? v.w : v.z) : ((hh & 1) ? v.y : v.x);
}

__global__ void __launch_bounds__(256) k_agg1f(const float* __restrict__ bias) {
    __shared__ float spl[512], spr[512], sq[512];
    __shared__ unsigned selmax[4];
    int tid = threadIdx.x;
    if (tid < 4) selmax[tid] = 0u;
    spl[tid] = g_pl2[tid];  spl[tid + 256] = g_pl2[tid + 256];
    spr[tid] = g_pr2[tid];  spr[tid + 256] = g_pr2[tid + 256];
    sq[tid]  = g_q[tid];    sq[tid + 256]  = g_q[tid + 256];
    __syncthreads();

    int gw = (blockIdx.x * 256 + tid) >> 5;
    int lane = tid & 31;
    bool valid = (gw < NN);
    int n = valid ? gw : 0;
    int beg = g_rowptr[n], end = valid ? g_rowptr[n + 1] : g_rowptr[n];
    float4 er4 = *(const float4*)&g_er[n * 4];

    int hh = lane >> 3;
    float erh = sel4(er4, hh);
    float mh = funord(g_elmax[hh]) + erh;
    mh = mh >= 0.f ? mh : 0.2f * mh;

    float a0 = 0.f, a1 = 0.f, a2 = 0.f, a3 = 0.f, sacc = 0.f;
    for (int j = beg; j < end; j++) {
        int s = g_csr[j];
        float4 el4 = *(const float4*)&g_el[s * 4];
        float e = sel4(el4, hh) + erh;
        e = e >= 0.f ? e : 0.2f * e;
        float p = __expf(e - mh);
        uint2 pk = *(const uint2*)&g_h[(size_t)s * 128 + lane * 4];
        float2 f0 = __half22float2(*(__half2*)&pk.x);
        float2 f1 = __half22float2(*(__half2*)&pk.y);
        a0 = fmaf(p, f0.x, a0); a1 = fmaf(p, f0.y, a1);
        a2 = fmaf(p, f1.x, a2); a3 = fmaf(p, f1.y, a3);
        sacc += p;
    }
    float inv = valid ? (1.f / sacc) : 0.f;
    int c0 = lane * 4;
    float4 bv = *(const float4*)&bias[c0];
    float y0 = fmaf(a0, inv, bv.x), y1 = fmaf(a1, inv, bv.y);
    float y2 = fmaf(a2, inv, bv.z), y3 = fmaf(a3, inv, bv.w);
    y0 = y0 >= 0.f ? y0 : 0.01f * y0;
    y1 = y1 >= 0.f ? y1 : 0.01f * y1;
    y2 = y2 >= 0.f ? y2 : 0.01f * y2;
    y3 = y3 >= 0.f ? y3 : 0.01f * y3;

    // layer-2 projections: per head h, dot over ALL 128 channels
    float el[4], er[4], zz[4];
#pragma unroll
    for (int h = 0; h < 4; h++) {
        const float* pl = spl + h * 128 + c0;
        const float* pr = spr + h * 128 + c0;
        const float* qq = sq + h * 128 + c0;
        el[h] = y0 * pl[0] + y1 * pl[1] + y2 * pl[2] + y3 * pl[3];
        er[h] = y0 * pr[0] + y1 * pr[1] + y2 * pr[2] + y3 * pr[3];
        zz[h] = y0 * qq[0] + y1 * qq[1] + y2 * qq[2] + y3 * qq[3];
    }
#pragma unroll
    for (int o = 16; o > 0; o >>= 1) {
#pragma unroll
        for (int h = 0; h < 4; h++) {
            el[h] += __shfl_xor_sync(0xffffffffu, el[h], o);
            er[h] += __shfl_xor_sync(0xffffffffu, er[h], o);
            zz[h] += __shfl_xor_sync(0xffffffffu, zz[h], o);
        }
    }
    if (valid && lane == 0) {
        g_el2[n] = make_float4(el[0], el[1], el[2], el[3]);
        g_er2[n] = make_float4(er[0], er[1], er[2], er[3]);
        g_z[n] = make_float4(zz[0], zz[1], zz[2], zz[3]);
#pragma unroll
        for (int h = 0; h < 4; h++) atomicMax(&selmax[h], ford(el[h]));
    }
    __syncthreads();
    if (tid < 4 && selmax[tid]) atomicMax(&g_elmax[4 + tid], selmax[tid]);
}

// ---------------- final aggregation + prediction: one THREAD per node ------------
__global__ void __launch_bounds__(256) k_aggF(float* __restrict__ out) {
    int n = blockIdx.x * blockDim.x + threadIdx.x;
    if (n >= NN) return;
    int beg = g_rowptr[n], end = g_rowptr[n + 1];
    float4 er4 = g_er2[n];

    float m0 = funord(g_elmax[4]) + er4.x; m0 = m0 >= 0.f ? m0 : 0.2f * m0;
    float m1 = funord(g_elmax[5]) + er4.y; m1 = m1 >= 0.f ? m1 : 0.2f * m1;
    float m2 = funord(g_elmax[6]) + er4.z; m2 = m2 >= 0.f ? m2 : 0.2f * m2;
    float m3 = funord(g_elmax[7]) + er4.w; m3 = m3 >= 0.f ? m3 : 0.2f * m3;

    float t0 = 0.f, t1 = 0.f, t2 = 0.f, t3 = 0.f;
    float S0 = 0.f, S1 = 0.f, S2 = 0.f, S3 = 0.f;
    for (int j = beg; j < end; j++) {
        int s = g_csr[j];
        float4 el4 = g_el2[s];
        float4 z4 = g_z[s];
        float e0 = el4.x + er4.x; e0 = e0 >= 0.f ? e0 : 0.2f * e0;
        float e1 = el4.y + er4.y; e1 = e1 >= 0.f ? e1 : 0.2f * e1;
        float e2 = el4.z + er4.z; e2 = e2 >= 0.f ? e2 : 0.2f * e2;
        float e3 = el4.w + er4.w; e3 = e3 >= 0.f ? e3 : 0.2f * e3;
        float p0 = __expf(e0 - m0), p1 = __expf(e1 - m1);
        float p2 = __expf(e2 - m2), p3 = __expf(e3 - m3);
        t0 = fmaf(p0, z4.x, t0); t1 = fmaf(p1, z4.y, t1);
        t2 = fmaf(p2, z4.z, t2); t3 = fmaf(p3, z4.w, t3);
        S0 += p0; S1 += p1; S2 += p2; S3 += p3;
    }
    out[n] = t0 / S0 + t1 / S1 + t2 / S2 + t3 / S3 + g_c0[0];
}

// ---------------- launch --------------------------------------------------------
extern "C" void kernel_launch(void* const* d_in, const int* in_sizes, int n_in,
                              void* d_out, int out_size) {
    const float* weights = (const float*)d_in[0];
    const float* linW    = (const float*)d_in[1];
    const float* linb    = (const float*)d_in[2];
    const float* fcW     = (const float*)d_in[3];
    const float* al      = (const float*)d_in[4];
    const float* ar      = (const float*)d_in[5];
    const float* cb      = (const float*)d_in[6];
    const float* pW      = (const float*)d_in[7];
    const float* pb      = (const float*)d_in[8];
    const int*   src     = (const int*)d_in[9];
    const int*   dst     = (const int*)d_in[10];
    float* out = (float*)d_out;

    void* p = nullptr;
    cudaGetSymbolAddress(&p, g_cnt);
    cudaMemsetAsync(p, 0, NN * sizeof(int));
    cudaGetSymbolAddress(&p, g_elmax);
    cudaMemsetAsync(p, 0, 8 * sizeof(unsigned));
    cudaGetSymbolAddress(&p, g_wmm);
    cudaMemsetAsync(p, 0x00, sizeof(unsigned));
    cudaMemsetAsync((char*)p + sizeof(unsigned), 0xFF, sizeof(unsigned));

    k_hist<<<(EE + 255) / 256, 256>>>(dst);
    k_scanA<<<SCAN_B, 1024>>>();
    k_scanB<<<1, 128>>>();
    k_scanC<<<SCAN_B, 1024>>>();
    k_scatter<<<(EE + NN + 255) / 256, 256>>>(src, dst);

    k_wmm<<<(NN + 255) / 256, 256>>>(weights);
    k_prep<<<1, 1024>>>(fcW, linW, linb, al, ar, cb);
    k_prep2<<<1, 128>>>(fcW + DD * DD);
    k_proj<<<1, 512>>>(fcW + 2 * DD * DD, al + 2 * DD, ar + 2 * DD, pW, pb, cb + 2 * DD);

    const int AB  = (NN * 32 + 255) / 256;   // warp-per-node kernels
    const int AB1 = (NN + 255) / 256;        // thread-per-node kernels

    k_agg0<<<AB1, 256>>>(weights);
    k_pw<<<AB, 256>>>(al + DD, ar + DD);
    k_agg1f<<<AB, 256>>>(cb + DD);
    k_aggF<<<AB1, 256>>>(out);
}